// round 9
// baseline (speedup 1.0000x reference)
#include <cuda_runtime.h>
#include <cuda.h>
#include <cstdint>

// ============================================================================
// Problem constants: N=8192 nodes, D_IN=D_OUT=128
// ============================================================================
#define NN 8192
#define DD 128

// Scratch (allocation-free rule: __device__ globals)
__device__ __align__(1024) float g_sup[NN * DD];       // X @ W
__device__ __align__(1024) float g_sprimeT[DD * NN];   // tf32-rounded d ⊙ (X@W), transposed [c][i]
__device__ __align__(1024) float g_dinv[NN];

// ============================================================================
// PTX helpers — only baseline (non sm_103a-gated) instructions.
// ============================================================================
__device__ __forceinline__ uint32_t smem_u32(const void* p) {
    uint32_t a;
    asm("{ .reg .u64 t; cvta.to.shared.u64 t, %1; cvt.u32.u64 %0, t; }" : "=r"(a) : "l"(p));
    return a;
}
__device__ __forceinline__ uint32_t elect_one_pred() {
    uint32_t p;
    asm volatile("{\n\t.reg .pred p;\n\telect.sync _|p, 0xFFFFFFFF;\n\tselp.b32 %0, 1, 0, p;\n\t}" : "=r"(p));
    return p;
}

#define MBARRIER_INIT(addr, cnt) \
    asm volatile("mbarrier.init.shared.b64 [%0], %1;" :: "r"((uint32_t)(addr)), "r"((uint32_t)(cnt)) : "memory")
#define MBARRIER_EXPECT_TX(addr, bytes) \
    asm volatile("mbarrier.arrive.expect_tx.shared.b64 _, [%0], %1;" :: "r"((uint32_t)(addr)), "r"((uint32_t)(bytes)) : "memory")
#define MBARRIER_ARRIVE(addr) \
    asm volatile("mbarrier.arrive.shared.b64 _, [%0];" :: "r"((uint32_t)(addr)) : "memory")

#define MBARRIER_WAIT_PARITY(mbar_smem_addr, phase_parity) do { \
    uint32_t _mbar = (uint32_t)(mbar_smem_addr); \
    uint32_t _parity = (uint32_t)(phase_parity); \
    uint32_t _done; \
    asm volatile("{\n\t.reg .pred p;\n\t" \
        "mbarrier.try_wait.parity.acquire.cta.shared::cta.b64 p, [%1], %2;\n\t" \
        "selp.b32 %0, 1, 0, p;\n\t}" \
        : "=r"(_done) : "r"(_mbar), "r"(_parity) : "memory"); \
    if (!_done) { \
        asm volatile("{\n\t.reg .pred P1;\n\t" \
            "WAIT_LOOP_%=:\n\t" \
            "mbarrier.try_wait.parity.acquire.cta.shared::cta.b64 P1, [%0], %1, 0x989680;\n\t" \
            "@P1 bra.uni WAIT_DONE_%=;\n\t" \
            "bra.uni WAIT_LOOP_%=;\n\t" \
            "WAIT_DONE_%=:\n\t}" \
            :: "r"(_mbar), "r"(_parity) : "memory"); \
    } \
} while(0)

#define MBARRIER_WAIT_PARITY_RELAXED(mbar_smem_addr, phase_parity) do { \
    uint32_t _mbar = (uint32_t)(mbar_smem_addr); \
    uint32_t _parity = (uint32_t)(phase_parity); \
    uint32_t _done; \
    asm volatile("{\n\t.reg .pred p;\n\t" \
        "mbarrier.try_wait.parity.relaxed.cta.shared::cta.b64 p, [%1], %2, 0x989680;\n\t" \
        "selp.b32 %0, 1, 0, p;\n\t}" \
        : "=r"(_done) : "r"(_mbar), "r"(_parity) : "memory"); \
    if (!_done) { \
        asm volatile("{\n\t.reg .pred P1;\n\t" \
            "WAIT_LOOP_%=:\n\t" \
            "mbarrier.try_wait.parity.relaxed.cta.shared::cta.b64 P1, [%0], %1, 0x989680;\n\t" \
            "@P1 bra.uni WAIT_DONE_%=;\n\t" \
            "bra.uni WAIT_LOOP_%=;\n\t" \
            "WAIT_DONE_%=:\n\t}" \
            :: "r"(_mbar), "r"(_parity) : "memory"); \
    } \
} while(0)

#define TMA_LOAD_2D(smem_addr, tmap_ptr, cx, cy, mbar) \
    asm volatile("cp.async.bulk.tensor.2d.shared::cta.global.tile.mbarrier::complete_tx::bytes " \
        "[%0], [%1, {%2, %3}], [%4];" \
        :: "r"((uint32_t)(smem_addr)), "l"(tmap_ptr), "r"((int32_t)(cx)), "r"((int32_t)(cy)), \
           "r"((uint32_t)(mbar)) : "memory")

// Plain ld.shared.b32 — raw fp32 bits fed to tf32 MMA (truncation; no cvt in hot loop)
__device__ __forceinline__ uint32_t lds_b32(uint32_t addr, int imm) {
    uint32_t v;
    asm volatile("ld.shared.b32 %0, [%1];" : "=r"(v) : "r"(addr + imm));
    return v;
}

// m16n8k8 tf32 HMMA (baseline PTX, works on plain sm_103 target)
__device__ __forceinline__ void mma_tf32(float* d, const uint32_t* a, const uint32_t* b) {
    asm volatile(
        "mma.sync.aligned.m16n8k8.row.col.f32.tf32.tf32.f32 "
        "{%0,%1,%2,%3}, {%4,%5,%6,%7}, {%8,%9}, {%0,%1,%2,%3};"
        : "+f"(d[0]), "+f"(d[1]), "+f"(d[2]), "+f"(d[3])
        : "r"(a[0]), "r"(a[1]), "r"(a[2]), "r"(a[3]), "r"(b[0]), "r"(b[1]));
}

// ============================================================================
// Kernel 1: support = X @ W    (one warp per row; 8 rows per 256-thread block)
// ============================================================================
__global__ void __launch_bounds__(256) support_kernel(const float* __restrict__ X,
                                                      const float* __restrict__ W,
                                                      float* __restrict__ sup) {
    __shared__ float xs[8][DD];
    int w = threadIdx.x >> 5;
    int lane = threadIdx.x & 31;
    int row = blockIdx.x * 8 + w;

    const float4* xr = (const float4*)(X + row * DD);
    ((float4*)xs[w])[lane] = xr[lane];
    __syncwarp();

    float4 acc = make_float4(0.f, 0.f, 0.f, 0.f);
    #pragma unroll 8
    for (int k = 0; k < DD; k++) {
        float xv = xs[w][k];
        float4 wv = *(const float4*)(W + k * DD + lane * 4);
        acc.x = fmaf(xv, wv.x, acc.x);
        acc.y = fmaf(xv, wv.y, acc.y);
        acc.z = fmaf(xv, wv.z, acc.z);
        acc.w = fmaf(xv, wv.w, acc.w);
    }
    *(float4*)(sup + row * DD + lane * 4) = acc;
}

// ============================================================================
// Kernel 2: d_inv_sqrt[i] = rsqrt(1 + rowsum(A[i,:]))   (one warp per row)
// ============================================================================
__global__ void __launch_bounds__(256) rowsum_kernel(const float4* __restrict__ A4,
                                                     float* __restrict__ dinv) {
    int row = blockIdx.x * 8 + (threadIdx.x >> 5);
    int lane = threadIdx.x & 31;
    const float4* rp = A4 + (size_t)row * (NN / 4);
    float s = 0.f;
    #pragma unroll 8
    for (int i = lane; i < NN / 4; i += 32) {
        float4 v = rp[i];
        s += (v.x + v.y) + (v.z + v.w);
    }
    #pragma unroll
    for (int o = 16; o > 0; o >>= 1) s += __shfl_xor_sync(0xFFFFFFFFu, s, o);
    if (lane == 0) dinv[row] = rsqrtf(s + 1.0f);
}

// ============================================================================
// Kernel 3: sprimeT = tf32_round(transpose(d ⊙ support))
// ============================================================================
__global__ void __launch_bounds__(256) scale_transpose_kernel(const float* __restrict__ sup,
                                                              const float* __restrict__ dinv,
                                                              float* __restrict__ sprimeT) {
    __shared__ float tile[32][33];
    int i0 = blockIdx.x * 32;
    int c0 = blockIdx.y * 32;
    int tx = threadIdx.x, ty = threadIdx.y;

    #pragma unroll
    for (int r = ty; r < 32; r += 8) {
        int i = i0 + r;
        float v = sup[i * DD + c0 + tx] * dinv[i];
        uint32_t u = __float_as_uint(v);
        asm("cvt.rna.tf32.f32 %0, %0;" : "+r"(u));
        tile[r][tx] = __uint_as_float(u);
    }
    __syncthreads();
    #pragma unroll
    for (int r = ty; r < 32; r += 8) {
        int c = c0 + r;
        sprimeT[(size_t)c * NN + i0 + tx] = tile[tx][r];
    }
}

// ============================================================================
// Kernel 4: out += d_i * (A @ sprime) [+ d_i^2*sup_i + bias on k-split 0]
// mma.sync tf32 GEMM, CTA tile M128 x N128, K split in 2, 6-stage TMA pipeline.
// 4 consumer warps in a 2x2 grid, 64x64 per warp (halves LDS crossbar bytes
// vs 8x(64x32): fragment duplication (wm+wn) drops 6 -> 4), + 1 producer warp.
// ============================================================================
#define STAGES 6
#define MTILE 128
#define KTILE 32
#define KSPLITS 2
#define KSPAN (NN / KSPLITS)        // 4096
#define GEMM_ITERS (KSPAN / KTILE)  // 128

#define OFF_FULL(s)  ((s) * 8)
#define OFF_EMPTY(s) (64 + (s) * 8)
#define TILE_BYTES 16384            // 128 rows * 128B
#define OFF_A(s)   (1024 + (s) * 2 * TILE_BYTES)
#define OFF_B(s)   (OFF_A(s) + TILE_BYTES)
#define GEMM_SMEM  (1024 + STAGES * 2 * TILE_BYTES)   // 197632 -> 1 CTA/SM

__global__ void __launch_bounds__(160, 1) gcn_gemm_kernel(
    const __grid_constant__ CUtensorMap tma_a,
    const __grid_constant__ CUtensorMap tma_b,
    const float* __restrict__ dinv,
    const float* __restrict__ sup,
    const float* __restrict__ bias,
    float* __restrict__ out)
{
    extern __shared__ char smem[];
    uint32_t sb = smem_u32(smem);
    const int tid = threadIdx.x, wid = tid >> 5, lane = tid & 31;
    const int m_base = blockIdx.x * MTILE;
    const int k_base = blockIdx.y * KSPAN;

    if (tid == 0) {
        #pragma unroll
        for (int s = 0; s < STAGES; s++) {
            MBARRIER_INIT(sb + OFF_FULL(s), 1);   // producer arrive + tx
            MBARRIER_INIT(sb + OFF_EMPTY(s), 4);  // one elect-arrive per consumer warp
        }
        asm volatile("fence.mbarrier_init.release.cluster;" ::: "memory");
    }
    __syncthreads();

    if (wid == 4) {
        // ---- TMA producer warp ----
        int st = 0, ph = 1;   // flipped phase: first empty-wait passes immediately
        for (int it = 0; it < GEMM_ITERS; it++) {
            MBARRIER_WAIT_PARITY_RELAXED(sb + OFF_EMPTY(st), ph);
            if (elect_one_pred()) {
                MBARRIER_EXPECT_TX(sb + OFF_FULL(st), 2 * TILE_BYTES);
                int kx = k_base + it * KTILE;
                TMA_LOAD_2D(sb + OFF_A(st), &tma_a, kx, m_base, sb + OFF_FULL(st));
                TMA_LOAD_2D(sb + OFF_B(st), &tma_b, kx, 0,      sb + OFF_FULL(st));
            }
            if (++st == STAGES) { st = 0; ph ^= 1; }
        }
        return;  // producer done; no epilogue work
    }

    // ---- consumer warps (0..3): 2x2 warp grid, 64x64 tile per warp ----
    const int g = lane >> 2;            // 0..7
    const int c = lane & 3;             // 0..3
    const int m_off = (wid & 1) * 64;
    const int n_off = (wid >> 1) * 64;
    const uint32_t swz = (uint32_t)g << 4;      // SW128 xor term (rows are 8-aligned)

    // Per-k-step word offsets (include swizzle XOR); k0 = ks*8
    uint32_t off0[4], off4[4];
    #pragma unroll
    for (int ks = 0; ks < 4; ks++) {
        off0[ks] = ((uint32_t)((ks * 8 + c) * 4)) ^ swz;
        off4[ks] = ((uint32_t)((ks * 8 + c + 4) * 4)) ^ swz;
    }
    // Fragment row base pointers (stage-0 based; stage adds imm offset)
    uint32_t qa[4], qb[8];
    #pragma unroll
    for (int i = 0; i < 4; i++)
        qa[i] = sb + OFF_A(0) + (uint32_t)(m_off + i * 16 + g) * 128u;
    #pragma unroll
    for (int i = 0; i < 8; i++)
        qb[i] = sb + OFF_B(0) + (uint32_t)(n_off + i * 8 + g) * 128u;

    float acc[4][8][4];
    #pragma unroll
    for (int mi = 0; mi < 4; mi++)
        #pragma unroll
        for (int ni = 0; ni < 8; ni++)
            #pragma unroll
            for (int d = 0; d < 4; d++) acc[mi][ni][d] = 0.f;

    int st = 0, ph = 0;
    for (int it = 0; it < GEMM_ITERS; it++) {
        MBARRIER_WAIT_PARITY(sb + OFF_FULL(st), ph);
        const int soff = st * 2 * TILE_BYTES;
        #pragma unroll
        for (int ks = 0; ks < 4; ks++) {
            uint32_t a[4][4];
            #pragma unroll
            for (int mi = 0; mi < 4; mi++) {
                uint32_t p0 = qa[mi] + off0[ks];
                uint32_t p4 = qa[mi] + off4[ks];
                a[mi][0] = lds_b32(p0, soff);          // row g,   k=c
                a[mi][1] = lds_b32(p0, soff + 1024);   // row g+8, k=c
                a[mi][2] = lds_b32(p4, soff);          // row g,   k=c+4
                a[mi][3] = lds_b32(p4, soff + 1024);   // row g+8, k=c+4
            }
            uint32_t b[8][2];
            #pragma unroll
            for (int ni = 0; ni < 8; ni++) {
                b[ni][0] = lds_b32(qb[ni] + off0[ks], soff);
                b[ni][1] = lds_b32(qb[ni] + off4[ks], soff);
            }
            #pragma unroll
            for (int mi = 0; mi < 4; mi++)
                #pragma unroll
                for (int ni = 0; ni < 8; ni++)
                    mma_tf32(acc[mi][ni], a[mi], b[ni]);
        }
        // All lanes' LDS for this stage issue before lane0's arrive (warp program
        // order), so a single elect-arrive per warp is sufficient (count=4).
        if (lane == 0) MBARRIER_ARRIVE(sb + OFF_EMPTY(st));
        if (++st == STAGES) { st = 0; ph ^= 1; }
    }

    // ---- epilogue: d_i scale, optional self-loop (dv^2 * sup) + bias, float2 atomics ----
    #pragma unroll
    for (int mi = 0; mi < 4; mi++) {
        int r0 = m_base + m_off + mi * 16 + g;
        int r1 = r0 + 8;
        float dv0 = dinv[r0];
        float dv1 = dinv[r1];
        #pragma unroll
        for (int ni = 0; ni < 8; ni++) {
            int col = n_off + ni * 8 + c * 2;
            float2 v0 = make_float2(dv0 * acc[mi][ni][0], dv0 * acc[mi][ni][1]);
            float2 v1 = make_float2(dv1 * acc[mi][ni][2], dv1 * acc[mi][ni][3]);
            if (blockIdx.y == 0) {
                float s00 = sup[r0 * DD + col], s01 = sup[r0 * DD + col + 1];
                float s10 = sup[r1 * DD + col], s11 = sup[r1 * DD + col + 1];
                v0.x += dv0 * dv0 * s00 + bias[col];
                v0.y += dv0 * dv0 * s01 + bias[col + 1];
                v1.x += dv1 * dv1 * s10 + bias[col];
                v1.y += dv1 * dv1 * s11 + bias[col + 1];
            }
            atomicAdd((float2*)&out[r0 * DD + col], v0);
            atomicAdd((float2*)&out[r1 * DD + col], v1);
        }
    }
}

// ============================================================================
// Host launcher
// ============================================================================
typedef CUresult (*PFN_tmapEncode)(CUtensorMap*, CUtensorMapDataType, cuuint32_t, void*,
                                   const cuuint64_t*, const cuuint64_t*, const cuuint32_t*,
                                   const cuuint32_t*, CUtensorMapInterleave, CUtensorMapSwizzle,
                                   CUtensorMapL2promotion, CUtensorMapFloatOOBfill);

extern "C" void kernel_launch(void* const* d_in, const int* in_sizes, int n_in,
                              void* d_out, int out_size) {
    const float* X    = (const float*)d_in[0];   // [8192,128]
    const float* A    = (const float*)d_in[1];   // [8192,8192]
    const float* W    = (const float*)d_in[2];   // [128,128]
    const float* bias = (const float*)d_in[3];   // [128]
    float* out = (float*)d_out;                  // [8192,128]

    float *sup, *sprimeT, *dinv;
    cudaGetSymbolAddress((void**)&sup,     g_sup);
    cudaGetSymbolAddress((void**)&sprimeT, g_sprimeT);
    cudaGetSymbolAddress((void**)&dinv,    g_dinv);

    // Resolve driver tensor-map encoder without a -lcuda link dependency.
    PFN_tmapEncode encode = nullptr;
    {
        void* fn = nullptr;
        cudaDriverEntryPointQueryResult qr;
        cudaGetDriverEntryPointByVersion("cuTensorMapEncodeTiled", &fn, 12000,
                                         cudaEnableDefault, &qr);
        encode = (PFN_tmapEncode)fn;
    }

    // TMA maps: inner dim = 32 fp32 = 128B (SW128 limit).
    CUtensorMap mapA, mapB;
    {
        cuuint64_t dims[2]  = {NN, NN};
        cuuint64_t strides[1] = {(cuuint64_t)NN * sizeof(float)};
        cuuint32_t box[2]   = {KTILE, MTILE};
        cuuint32_t es[2]    = {1, 1};
        encode(&mapA, CU_TENSOR_MAP_DATA_TYPE_FLOAT32, 2, (void*)A,
               dims, strides, box, es,
               CU_TENSOR_MAP_INTERLEAVE_NONE, CU_TENSOR_MAP_SWIZZLE_128B,
               CU_TENSOR_MAP_L2_PROMOTION_L2_128B, CU_TENSOR_MAP_FLOAT_OOB_FILL_NONE);
    }
    {
        cuuint64_t dims[2]  = {NN, DD};
        cuuint64_t strides[1] = {(cuuint64_t)NN * sizeof(float)};
        cuuint32_t box[2]   = {KTILE, 128};
        cuuint32_t es[2]    = {1, 1};
        encode(&mapB, CU_TENSOR_MAP_DATA_TYPE_FLOAT32, 2, (void*)sprimeT,
               dims, strides, box, es,
               CU_TENSOR_MAP_INTERLEAVE_NONE, CU_TENSOR_MAP_SWIZZLE_128B,
               CU_TENSOR_MAP_L2_PROMOTION_L2_128B, CU_TENSOR_MAP_FLOAT_OOB_FILL_NONE);
    }

    cudaFuncSetAttribute(gcn_gemm_kernel, cudaFuncAttributeMaxDynamicSharedMemorySize, GEMM_SMEM);

    // Pipeline of kernels on the default (captured) stream.
    support_kernel<<<NN / 8, 256>>>(X, W, sup);
    rowsum_kernel<<<NN / 8, 256>>>((const float4*)A, dinv);
    scale_transpose_kernel<<<dim3(NN / 32, DD / 32), dim3(32, 8)>>>(sup, dinv, sprimeT);
    cudaMemsetAsync(d_out, 0, (size_t)NN * DD * sizeof(float));
    gcn_gemm_kernel<<<dim3(NN / MTILE, KSPLITS), 160, GEMM_SMEM>>>(mapA, mapB, dinv, sup, bias, out);
}

// round 13
// speedup vs baseline: 1.0500x; 1.0500x over previous
#include <cuda_runtime.h>
#include <cuda.h>
#include <cstdint>

// ============================================================================
// Problem constants: N=8192 nodes, D_IN=D_OUT=128
// ============================================================================
#define NN 8192
#define DD 128

// Scratch (allocation-free rule: __device__ globals)
__device__ __align__(1024) float g_sup[NN * DD];       // X @ W
__device__ __align__(1024) float g_sprimeT[DD * NN];   // tf32-rounded d ⊙ (X@W), transposed [c][i]
__device__ __align__(1024) float g_dinv[NN];

// ============================================================================
// PTX helpers — only baseline (non sm_103a-gated) instructions.
// ============================================================================
__device__ __forceinline__ uint32_t smem_u32(const void* p) {
    uint32_t a;
    asm("{ .reg .u64 t; cvta.to.shared.u64 t, %1; cvt.u32.u64 %0, t; }" : "=r"(a) : "l"(p));
    return a;
}
__device__ __forceinline__ uint32_t elect_one_pred() {
    uint32_t p;
    asm volatile("{\n\t.reg .pred p;\n\telect.sync _|p, 0xFFFFFFFF;\n\tselp.b32 %0, 1, 0, p;\n\t}" : "=r"(p));
    return p;
}

#define MBARRIER_INIT(addr, cnt) \
    asm volatile("mbarrier.init.shared.b64 [%0], %1;" :: "r"((uint32_t)(addr)), "r"((uint32_t)(cnt)) : "memory")
#define MBARRIER_EXPECT_TX(addr, bytes) \
    asm volatile("mbarrier.arrive.expect_tx.shared.b64 _, [%0], %1;" :: "r"((uint32_t)(addr)), "r"((uint32_t)(bytes)) : "memory")
#define MBARRIER_ARRIVE(addr) \
    asm volatile("mbarrier.arrive.shared.b64 _, [%0];" :: "r"((uint32_t)(addr)) : "memory")

#define MBARRIER_WAIT_PARITY(mbar_smem_addr, phase_parity) do { \
    uint32_t _mbar = (uint32_t)(mbar_smem_addr); \
    uint32_t _parity = (uint32_t)(phase_parity); \
    uint32_t _done; \
    asm volatile("{\n\t.reg .pred p;\n\t" \
        "mbarrier.try_wait.parity.acquire.cta.shared::cta.b64 p, [%1], %2;\n\t" \
        "selp.b32 %0, 1, 0, p;\n\t}" \
        : "=r"(_done) : "r"(_mbar), "r"(_parity) : "memory"); \
    if (!_done) { \
        asm volatile("{\n\t.reg .pred P1;\n\t" \
            "WAIT_LOOP_%=:\n\t" \
            "mbarrier.try_wait.parity.acquire.cta.shared::cta.b64 P1, [%0], %1, 0x989680;\n\t" \
            "@P1 bra.uni WAIT_DONE_%=;\n\t" \
            "bra.uni WAIT_LOOP_%=;\n\t" \
            "WAIT_DONE_%=:\n\t}" \
            :: "r"(_mbar), "r"(_parity) : "memory"); \
    } \
} while(0)

#define MBARRIER_WAIT_PARITY_RELAXED(mbar_smem_addr, phase_parity) do { \
    uint32_t _mbar = (uint32_t)(mbar_smem_addr); \
    uint32_t _parity = (uint32_t)(phase_parity); \
    uint32_t _done; \
    asm volatile("{\n\t.reg .pred p;\n\t" \
        "mbarrier.try_wait.parity.relaxed.cta.shared::cta.b64 p, [%1], %2, 0x989680;\n\t" \
        "selp.b32 %0, 1, 0, p;\n\t}" \
        : "=r"(_done) : "r"(_mbar), "r"(_parity) : "memory"); \
    if (!_done) { \
        asm volatile("{\n\t.reg .pred P1;\n\t" \
            "WAIT_LOOP_%=:\n\t" \
            "mbarrier.try_wait.parity.relaxed.cta.shared::cta.b64 P1, [%0], %1, 0x989680;\n\t" \
            "@P1 bra.uni WAIT_DONE_%=;\n\t" \
            "bra.uni WAIT_LOOP_%=;\n\t" \
            "WAIT_DONE_%=:\n\t}" \
            :: "r"(_mbar), "r"(_parity) : "memory"); \
    } \
} while(0)

#define TMA_LOAD_2D(smem_addr, tmap_ptr, cx, cy, mbar) \
    asm volatile("cp.async.bulk.tensor.2d.shared::cta.global.tile.mbarrier::complete_tx::bytes " \
        "[%0], [%1, {%2, %3}], [%4];" \
        :: "r"((uint32_t)(smem_addr)), "l"(tmap_ptr), "r"((int32_t)(cx)), "r"((int32_t)(cy)), \
           "r"((uint32_t)(mbar)) : "memory")

// Plain ld.shared.b32 — raw fp32 bits fed to tf32 MMA (truncation; no cvt in hot loop)
__device__ __forceinline__ uint32_t lds_b32(uint32_t addr, int imm) {
    uint32_t v;
    asm volatile("ld.shared.b32 %0, [%1];" : "=r"(v) : "r"(addr + imm));
    return v;
}

// m16n8k8 tf32 HMMA (baseline PTX, works on plain sm_103 target)
__device__ __forceinline__ void mma_tf32(float* d, const uint32_t* a, const uint32_t* b) {
    asm volatile(
        "mma.sync.aligned.m16n8k8.row.col.f32.tf32.tf32.f32 "
        "{%0,%1,%2,%3}, {%4,%5,%6,%7}, {%8,%9}, {%0,%1,%2,%3};"
        : "+f"(d[0]), "+f"(d[1]), "+f"(d[2]), "+f"(d[3])
        : "r"(a[0]), "r"(a[1]), "r"(a[2]), "r"(a[3]), "r"(b[0]), "r"(b[1]));
}

// ============================================================================
// Kernel 1: support = X @ W    (one warp per row; 8 rows per 256-thread block)
// ============================================================================
__global__ void __launch_bounds__(256) support_kernel(const float* __restrict__ X,
                                                      const float* __restrict__ W,
                                                      float* __restrict__ sup) {
    __shared__ float xs[8][DD];
    int w = threadIdx.x >> 5;
    int lane = threadIdx.x & 31;
    int row = blockIdx.x * 8 + w;

    const float4* xr = (const float4*)(X + row * DD);
    ((float4*)xs[w])[lane] = xr[lane];
    __syncwarp();

    float4 acc = make_float4(0.f, 0.f, 0.f, 0.f);
    #pragma unroll 8
    for (int k = 0; k < DD; k++) {
        float xv = xs[w][k];
        float4 wv = *(const float4*)(W + k * DD + lane * 4);
        acc.x = fmaf(xv, wv.x, acc.x);
        acc.y = fmaf(xv, wv.y, acc.y);
        acc.z = fmaf(xv, wv.z, acc.z);
        acc.w = fmaf(xv, wv.w, acc.w);
    }
    *(float4*)(sup + row * DD + lane * 4) = acc;
}

// ============================================================================
// Kernel 2: d_inv_sqrt[i] = rsqrt(1 + rowsum(A[i,:]))   (one warp per row)
// ============================================================================
__global__ void __launch_bounds__(256) rowsum_kernel(const float4* __restrict__ A4,
                                                     float* __restrict__ dinv) {
    int row = blockIdx.x * 8 + (threadIdx.x >> 5);
    int lane = threadIdx.x & 31;
    const float4* rp = A4 + (size_t)row * (NN / 4);
    float s = 0.f;
    #pragma unroll 8
    for (int i = lane; i < NN / 4; i += 32) {
        float4 v = rp[i];
        s += (v.x + v.y) + (v.z + v.w);
    }
    #pragma unroll
    for (int o = 16; o > 0; o >>= 1) s += __shfl_xor_sync(0xFFFFFFFFu, s, o);
    if (lane == 0) dinv[row] = rsqrtf(s + 1.0f);
}

// ============================================================================
// Kernel 3: sprimeT = tf32_round(transpose(d ⊙ support))
// ============================================================================
__global__ void __launch_bounds__(256) scale_transpose_kernel(const float* __restrict__ sup,
                                                              const float* __restrict__ dinv,
                                                              float* __restrict__ sprimeT) {
    __shared__ float tile[32][33];
    int i0 = blockIdx.x * 32;
    int c0 = blockIdx.y * 32;
    int tx = threadIdx.x, ty = threadIdx.y;

    #pragma unroll
    for (int r = ty; r < 32; r += 8) {
        int i = i0 + r;
        float v = sup[i * DD + c0 + tx] * dinv[i];
        uint32_t u = __float_as_uint(v);
        asm("cvt.rna.tf32.f32 %0, %0;" : "+r"(u));
        tile[r][tx] = __uint_as_float(u);
    }
    __syncthreads();
    #pragma unroll
    for (int r = ty; r < 32; r += 8) {
        int c = c0 + r;
        sprimeT[(size_t)c * NN + i0 + tx] = tile[tx][r];
    }
}

// ============================================================================
// Kernel 4: out += d_i * (A @ sprime) [+ d_i^2*sup_i + bias on k-split 0]
// mma.sync tf32 GEMM, CTA tile M128 x N128, K split in 2, KTILE=64 with a
// 3-stage TMA pipeline (same smem as 6xK32, HALF the barrier crossings --
// the fixed per-stage wait/refill bubble is amortized over 2048 tensor cyc).
// 8 compute warps (2x4 MxN, 64x32 per warp) + 1 producer warp = 288 threads.
// ============================================================================
#define STAGES 3
#define MTILE 128
#define KTILE 64
#define KSPLITS 2
#define KSPAN (NN / KSPLITS)        // 4096
#define GEMM_ITERS (KSPAN / KTILE)  // 64

#define OFF_FULL(s)  ((s) * 8)
#define OFF_EMPTY(s) (64 + (s) * 8)
#define BOX_BYTES 16384             // one TMA box: 128 rows * 32 floats
#define A_TILE_BYTES 32768          // two boxes (k 0-31, k 32-63)
#define STAGE_BYTES  65536          // A + B
#define OFF_A(s)   (1024 + (s) * STAGE_BYTES)
#define OFF_B(s)   (OFF_A(s) + A_TILE_BYTES)
#define GEMM_SMEM  (1024 + STAGES * STAGE_BYTES)   // 197632 -> 1 CTA/SM

__global__ void __launch_bounds__(288, 1) gcn_gemm_kernel(
    const __grid_constant__ CUtensorMap tma_a,
    const __grid_constant__ CUtensorMap tma_b,
    const float* __restrict__ dinv,
    const float* __restrict__ sup,
    const float* __restrict__ bias,
    float* __restrict__ out)
{
    extern __shared__ char smem[];
    uint32_t sb = smem_u32(smem);
    const int tid = threadIdx.x, wid = tid >> 5, lane = tid & 31;
    const int m_base = blockIdx.x * MTILE;
    const int k_base = blockIdx.y * KSPAN;

    if (tid == 0) {
        #pragma unroll
        for (int s = 0; s < STAGES; s++) {
            MBARRIER_INIT(sb + OFF_FULL(s), 1);   // producer arrive + tx
            MBARRIER_INIT(sb + OFF_EMPTY(s), 8);  // one elect-arrive per consumer warp
        }
        asm volatile("fence.mbarrier_init.release.cluster;" ::: "memory");
    }
    __syncthreads();

    if (wid == 8) {
        // ---- TMA producer warp: 4 boxes per stage (A k-lo/hi, B k-lo/hi) ----
        int st = 0, ph = 1;   // flipped phase: first empty-wait passes immediately
        for (int it = 0; it < GEMM_ITERS; it++) {
            MBARRIER_WAIT_PARITY_RELAXED(sb + OFF_EMPTY(st), ph);
            if (elect_one_pred()) {
                MBARRIER_EXPECT_TX(sb + OFF_FULL(st), STAGE_BYTES);
                int kx = k_base + it * KTILE;
                TMA_LOAD_2D(sb + OFF_A(st),             &tma_a, kx,      m_base, sb + OFF_FULL(st));
                TMA_LOAD_2D(sb + OFF_A(st) + BOX_BYTES, &tma_a, kx + 32, m_base, sb + OFF_FULL(st));
                TMA_LOAD_2D(sb + OFF_B(st),             &tma_b, kx,      0,      sb + OFF_FULL(st));
                TMA_LOAD_2D(sb + OFF_B(st) + BOX_BYTES, &tma_b, kx + 32, 0,      sb + OFF_FULL(st));
            }
            if (++st == STAGES) { st = 0; ph ^= 1; }
        }
        return;  // producer done; no epilogue work
    }

    // ---- consumer warps (0..7): 2x4 (M x N) warp grid, 64x32 per warp ----
    const int g = lane >> 2;            // 0..7
    const int c = lane & 3;             // 0..3
    const int m_off = (wid & 1) * 64;
    const int n_off = (wid >> 1) * 32;
    const uint32_t swz = (uint32_t)g << 4;      // SW128 xor term (rows are 8-aligned)

    // Within-box per-k-step word offsets (include swizzle XOR); box k = ks&3
    uint32_t off0[4], off4[4];
    #pragma unroll
    for (int ks = 0; ks < 4; ks++) {
        off0[ks] = ((uint32_t)((ks * 8 + c) * 4)) ^ swz;
        off4[ks] = ((uint32_t)((ks * 8 + c + 4) * 4)) ^ swz;
    }
    // Fragment row base pointers (stage-0 based; stage/box add imm offsets)
    uint32_t qa[4], qb[4];
    #pragma unroll
    for (int i = 0; i < 4; i++) {
        qa[i] = sb + OFF_A(0) + (uint32_t)(m_off + i * 16 + g) * 128u;
        qb[i] = sb + OFF_B(0) + (uint32_t)(n_off + i * 8 + g) * 128u;
    }

    float acc[4][4][4];
    #pragma unroll
    for (int mi = 0; mi < 4; mi++)
        #pragma unroll
        for (int ni = 0; ni < 4; ni++)
            #pragma unroll
            for (int d = 0; d < 4; d++) acc[mi][ni][d] = 0.f;

    int st = 0, ph = 0;
    for (int it = 0; it < GEMM_ITERS; it++) {
        MBARRIER_WAIT_PARITY(sb + OFF_FULL(st), ph);
        const int soff = st * STAGE_BYTES;
        #pragma unroll
        for (int ks = 0; ks < 8; ks++) {
            const int koff = soff + ((ks >= 4) ? BOX_BYTES : 0);
            const int kk = ks & 3;
            uint32_t a[4][4];
            #pragma unroll
            for (int mi = 0; mi < 4; mi++) {
                uint32_t p0 = qa[mi] + off0[kk];
                uint32_t p4 = qa[mi] + off4[kk];
                a[mi][0] = lds_b32(p0, koff);          // row g,   k=c
                a[mi][1] = lds_b32(p0, koff + 1024);   // row g+8, k=c
                a[mi][2] = lds_b32(p4, koff);          // row g,   k=c+4
                a[mi][3] = lds_b32(p4, koff + 1024);   // row g+8, k=c+4
            }
            uint32_t b[4][2];
            #pragma unroll
            for (int ni = 0; ni < 4; ni++) {
                b[ni][0] = lds_b32(qb[ni] + off0[kk], koff);
                b[ni][1] = lds_b32(qb[ni] + off4[kk], koff);
            }
            #pragma unroll
            for (int mi = 0; mi < 4; mi++)
                #pragma unroll
                for (int ni = 0; ni < 4; ni++)
                    mma_tf32(acc[mi][ni], a[mi], b[ni]);
        }
        // All lanes' LDS for this stage issue before lane0's arrive (warp program
        // order), so a single elect-arrive per warp is sufficient (count=8).
        if (lane == 0) MBARRIER_ARRIVE(sb + OFF_EMPTY(st));
        if (++st == STAGES) { st = 0; ph ^= 1; }
    }

    // ---- epilogue: d_i scale, optional self-loop (dv^2 * sup) + bias, float2 atomics ----
    #pragma unroll
    for (int mi = 0; mi < 4; mi++) {
        int r0 = m_base + m_off + mi * 16 + g;
        int r1 = r0 + 8;
        float dv0 = dinv[r0];
        float dv1 = dinv[r1];
        #pragma unroll
        for (int ni = 0; ni < 4; ni++) {
            int col = n_off + ni * 8 + c * 2;
            float2 v0 = make_float2(dv0 * acc[mi][ni][0], dv0 * acc[mi][ni][1]);
            float2 v1 = make_float2(dv1 * acc[mi][ni][2], dv1 * acc[mi][ni][3]);
            if (blockIdx.y == 0) {
                float s00 = sup[r0 * DD + col], s01 = sup[r0 * DD + col + 1];
                float s10 = sup[r1 * DD + col], s11 = sup[r1 * DD + col + 1];
                v0.x += dv0 * dv0 * s00 + bias[col];
                v0.y += dv0 * dv0 * s01 + bias[col + 1];
                v1.x += dv1 * dv1 * s10 + bias[col];
                v1.y += dv1 * dv1 * s11 + bias[col + 1];
            }
            atomicAdd((float2*)&out[r0 * DD + col], v0);
            atomicAdd((float2*)&out[r1 * DD + col], v1);
        }
    }
}

// ============================================================================
// Host launcher
// ============================================================================
typedef CUresult (*PFN_tmapEncode)(CUtensorMap*, CUtensorMapDataType, cuuint32_t, void*,
                                   const cuuint64_t*, const cuuint64_t*, const cuuint32_t*,
                                   const cuuint32_t*, CUtensorMapInterleave, CUtensorMapSwizzle,
                                   CUtensorMapL2promotion, CUtensorMapFloatOOBfill);

extern "C" void kernel_launch(void* const* d_in, const int* in_sizes, int n_in,
                              void* d_out, int out_size) {
    const float* X    = (const float*)d_in[0];   // [8192,128]
    const float* A    = (const float*)d_in[1];   // [8192,8192]
    const float* W    = (const float*)d_in[2];   // [128,128]
    const float* bias = (const float*)d_in[3];   // [128]
    float* out = (float*)d_out;                  // [8192,128]

    float *sup, *sprimeT, *dinv;
    cudaGetSymbolAddress((void**)&sup,     g_sup);
    cudaGetSymbolAddress((void**)&sprimeT, g_sprimeT);
    cudaGetSymbolAddress((void**)&dinv,    g_dinv);

    // Resolve driver tensor-map encoder without a -lcuda link dependency.
    PFN_tmapEncode encode = nullptr;
    {
        void* fn = nullptr;
        cudaDriverEntryPointQueryResult qr;
        cudaGetDriverEntryPointByVersion("cuTensorMapEncodeTiled", &fn, 12000,
                                         cudaEnableDefault, &qr);
        encode = (PFN_tmapEncode)fn;
    }

    // TMA maps: inner dim = 32 fp32 = 128B (SW128 limit), 128 rows per box.
    CUtensorMap mapA, mapB;
    {
        cuuint64_t dims[2]  = {NN, NN};
        cuuint64_t strides[1] = {(cuuint64_t)NN * sizeof(float)};
        cuuint32_t box[2]   = {32, MTILE};
        cuuint32_t es[2]    = {1, 1};
        encode(&mapA, CU_TENSOR_MAP_DATA_TYPE_FLOAT32, 2, (void*)A,
               dims, strides, box, es,
               CU_TENSOR_MAP_INTERLEAVE_NONE, CU_TENSOR_MAP_SWIZZLE_128B,
               CU_TENSOR_MAP_L2_PROMOTION_L2_128B, CU_TENSOR_MAP_FLOAT_OOB_FILL_NONE);
    }
    {
        cuuint64_t dims[2]  = {NN, DD};
        cuuint64_t strides[1] = {(cuuint64_t)NN * sizeof(float)};
        cuuint32_t box[2]   = {32, 128};
        cuuint32_t es[2]    = {1, 1};
        encode(&mapB, CU_TENSOR_MAP_DATA_TYPE_FLOAT32, 2, (void*)sprimeT,
               dims, strides, box, es,
               CU_TENSOR_MAP_INTERLEAVE_NONE, CU_TENSOR_MAP_SWIZZLE_128B,
               CU_TENSOR_MAP_L2_PROMOTION_L2_128B, CU_TENSOR_MAP_FLOAT_OOB_FILL_NONE);
    }

    cudaFuncSetAttribute(gcn_gemm_kernel, cudaFuncAttributeMaxDynamicSharedMemorySize, GEMM_SMEM);

    // Pipeline of kernels on the default (captured) stream.
    support_kernel<<<NN / 8, 256>>>(X, W, sup);
    rowsum_kernel<<<NN / 8, 256>>>((const float4*)A, dinv);
    scale_transpose_kernel<<<dim3(NN / 32, DD / 32), dim3(32, 8)>>>(sup, dinv, sprimeT);
    cudaMemsetAsync(d_out, 0, (size_t)NN * DD * sizeof(float));
    gcn_gemm_kernel<<<dim3(NN / MTILE, KSPLITS), 288, GEMM_SMEM>>>(mapA, mapB, dinv, sup, bias, out);
}

// round 14
// speedup vs baseline: 1.0999x; 1.0475x over previous
#include <cuda_runtime.h>
#include <cuda.h>
#include <cstdint>

// ============================================================================
// Problem constants: N=8192 nodes, D_IN=D_OUT=128
// ============================================================================
#define NN 8192
#define DD 128

// Scratch (allocation-free rule: __device__ globals)
__device__ __align__(1024) float g_sup[NN * DD];       // X @ W
__device__ __align__(1024) float g_sprimeT[DD * NN];   // tf32-rounded d ⊙ (X@W), transposed [c][i]
__device__ __align__(1024) float g_dinv[NN];

// ============================================================================
// PTX helpers — only baseline (non sm_103a-gated) instructions.
// ============================================================================
__device__ __forceinline__ uint32_t smem_u32(const void* p) {
    uint32_t a;
    asm("{ .reg .u64 t; cvta.to.shared.u64 t, %1; cvt.u32.u64 %0, t; }" : "=r"(a) : "l"(p));
    return a;
}
__device__ __forceinline__ uint32_t elect_one_pred() {
    uint32_t p;
    asm volatile("{\n\t.reg .pred p;\n\telect.sync _|p, 0xFFFFFFFF;\n\tselp.b32 %0, 1, 0, p;\n\t}" : "=r"(p));
    return p;
}

#define MBARRIER_INIT(addr, cnt) \
    asm volatile("mbarrier.init.shared.b64 [%0], %1;" :: "r"((uint32_t)(addr)), "r"((uint32_t)(cnt)) : "memory")
#define MBARRIER_EXPECT_TX(addr, bytes) \
    asm volatile("mbarrier.arrive.expect_tx.shared.b64 _, [%0], %1;" :: "r"((uint32_t)(addr)), "r"((uint32_t)(bytes)) : "memory")
#define MBARRIER_ARRIVE(addr) \
    asm volatile("mbarrier.arrive.shared.b64 _, [%0];" :: "r"((uint32_t)(addr)) : "memory")

#define MBARRIER_WAIT_PARITY(mbar_smem_addr, phase_parity) do { \
    uint32_t _mbar = (uint32_t)(mbar_smem_addr); \
    uint32_t _parity = (uint32_t)(phase_parity); \
    uint32_t _done; \
    asm volatile("{\n\t.reg .pred p;\n\t" \
        "mbarrier.try_wait.parity.acquire.cta.shared::cta.b64 p, [%1], %2;\n\t" \
        "selp.b32 %0, 1, 0, p;\n\t}" \
        : "=r"(_done) : "r"(_mbar), "r"(_parity) : "memory"); \
    if (!_done) { \
        asm volatile("{\n\t.reg .pred P1;\n\t" \
            "WAIT_LOOP_%=:\n\t" \
            "mbarrier.try_wait.parity.acquire.cta.shared::cta.b64 P1, [%0], %1, 0x989680;\n\t" \
            "@P1 bra.uni WAIT_DONE_%=;\n\t" \
            "bra.uni WAIT_LOOP_%=;\n\t" \
            "WAIT_DONE_%=:\n\t}" \
            :: "r"(_mbar), "r"(_parity) : "memory"); \
    } \
} while(0)

#define MBARRIER_WAIT_PARITY_RELAXED(mbar_smem_addr, phase_parity) do { \
    uint32_t _mbar = (uint32_t)(mbar_smem_addr); \
    uint32_t _parity = (uint32_t)(phase_parity); \
    uint32_t _done; \
    asm volatile("{\n\t.reg .pred p;\n\t" \
        "mbarrier.try_wait.parity.relaxed.cta.shared::cta.b64 p, [%1], %2, 0x989680;\n\t" \
        "selp.b32 %0, 1, 0, p;\n\t}" \
        : "=r"(_done) : "r"(_mbar), "r"(_parity) : "memory"); \
    if (!_done) { \
        asm volatile("{\n\t.reg .pred P1;\n\t" \
            "WAIT_LOOP_%=:\n\t" \
            "mbarrier.try_wait.parity.relaxed.cta.shared::cta.b64 P1, [%0], %1, 0x989680;\n\t" \
            "@P1 bra.uni WAIT_DONE_%=;\n\t" \
            "bra.uni WAIT_LOOP_%=;\n\t" \
            "WAIT_DONE_%=:\n\t}" \
            :: "r"(_mbar), "r"(_parity) : "memory"); \
    } \
} while(0)

#define TMA_LOAD_2D(smem_addr, tmap_ptr, cx, cy, mbar) \
    asm volatile("cp.async.bulk.tensor.2d.shared::cta.global.tile.mbarrier::complete_tx::bytes " \
        "[%0], [%1, {%2, %3}], [%4];" \
        :: "r"((uint32_t)(smem_addr)), "l"(tmap_ptr), "r"((int32_t)(cx)), "r"((int32_t)(cy)), \
           "r"((uint32_t)(mbar)) : "memory")

// Plain ld.shared.b32 — raw fp32 bits fed to tf32 MMA (truncation; no cvt in hot loop)
__device__ __forceinline__ uint32_t lds_b32(uint32_t addr, int imm) {
    uint32_t v;
    asm volatile("ld.shared.b32 %0, [%1];" : "=r"(v) : "r"(addr + imm));
    return v;
}

// m16n8k8 tf32 HMMA (baseline PTX, works on plain sm_103 target)
__device__ __forceinline__ void mma_tf32(float* d, const uint32_t* a, const uint32_t* b) {
    asm volatile(
        "mma.sync.aligned.m16n8k8.row.col.f32.tf32.tf32.f32 "
        "{%0,%1,%2,%3}, {%4,%5,%6,%7}, {%8,%9}, {%0,%1,%2,%3};"
        : "+f"(d[0]), "+f"(d[1]), "+f"(d[2]), "+f"(d[3])
        : "r"(a[0]), "r"(a[1]), "r"(a[2]), "r"(a[3]), "r"(b[0]), "r"(b[1]));
}

// ============================================================================
// Kernel 1: support = X @ W    (one warp per row; 8 rows per 256-thread block)
// ============================================================================
__global__ void __launch_bounds__(256) support_kernel(const float* __restrict__ X,
                                                      const float* __restrict__ W,
                                                      float* __restrict__ sup) {
    __shared__ float xs[8][DD];
    int w = threadIdx.x >> 5;
    int lane = threadIdx.x & 31;
    int row = blockIdx.x * 8 + w;

    const float4* xr = (const float4*)(X + row * DD);
    ((float4*)xs[w])[lane] = xr[lane];
    __syncwarp();

    float4 acc = make_float4(0.f, 0.f, 0.f, 0.f);
    #pragma unroll 8
    for (int k = 0; k < DD; k++) {
        float xv = xs[w][k];
        float4 wv = *(const float4*)(W + k * DD + lane * 4);
        acc.x = fmaf(xv, wv.x, acc.x);
        acc.y = fmaf(xv, wv.y, acc.y);
        acc.z = fmaf(xv, wv.z, acc.z);
        acc.w = fmaf(xv, wv.w, acc.w);
    }
    *(float4*)(sup + row * DD + lane * 4) = acc;
}

// ============================================================================
// Kernel 2: d_inv_sqrt[i] = rsqrt(1 + rowsum(A[i,:]))
// One 256-thread block per row; 8 fully-unrolled float4 loads per thread
// (8 x 16B in flight per thread -> DRAM-latency covered, MLP-saturated).
// ============================================================================
__global__ void __launch_bounds__(256) rowsum_kernel(const float4* __restrict__ A4,
                                                     float* __restrict__ dinv) {
    __shared__ float wsum[8];
    const int row = blockIdx.x;
    const int t = threadIdx.x;
    const int w = t >> 5, lane = t & 31;
    const float4* rp = A4 + (size_t)row * (NN / 4);   // 2048 float4 per row

    float4 v0 = rp[t];
    float4 v1 = rp[t + 256];
    float4 v2 = rp[t + 512];
    float4 v3 = rp[t + 768];
    float4 v4 = rp[t + 1024];
    float4 v5 = rp[t + 1280];
    float4 v6 = rp[t + 1536];
    float4 v7 = rp[t + 1792];

    float s = ((v0.x + v0.y) + (v0.z + v0.w)) + ((v1.x + v1.y) + (v1.z + v1.w))
            + ((v2.x + v2.y) + (v2.z + v2.w)) + ((v3.x + v3.y) + (v3.z + v3.w))
            + ((v4.x + v4.y) + (v4.z + v4.w)) + ((v5.x + v5.y) + (v5.z + v5.w))
            + ((v6.x + v6.y) + (v6.z + v6.w)) + ((v7.x + v7.y) + (v7.z + v7.w));

    #pragma unroll
    for (int o = 16; o > 0; o >>= 1) s += __shfl_xor_sync(0xFFFFFFFFu, s, o);
    if (lane == 0) wsum[w] = s;
    __syncthreads();
    if (t == 0) {
        float tot = (wsum[0] + wsum[1]) + (wsum[2] + wsum[3])
                  + (wsum[4] + wsum[5]) + (wsum[6] + wsum[7]);
        dinv[row] = rsqrtf(tot + 1.0f);
    }
}

// ============================================================================
// Kernel 3: sprimeT = tf32_round(transpose(d ⊙ support))
// ============================================================================
__global__ void __launch_bounds__(256) scale_transpose_kernel(const float* __restrict__ sup,
                                                              const float* __restrict__ dinv,
                                                              float* __restrict__ sprimeT) {
    __shared__ float tile[32][33];
    int i0 = blockIdx.x * 32;
    int c0 = blockIdx.y * 32;
    int tx = threadIdx.x, ty = threadIdx.y;

    #pragma unroll
    for (int r = ty; r < 32; r += 8) {
        int i = i0 + r;
        float v = sup[i * DD + c0 + tx] * dinv[i];
        uint32_t u = __float_as_uint(v);
        asm("cvt.rna.tf32.f32 %0, %0;" : "+r"(u));
        tile[r][tx] = __uint_as_float(u);
    }
    __syncthreads();
    #pragma unroll
    for (int r = ty; r < 32; r += 8) {
        int c = c0 + r;
        sprimeT[(size_t)c * NN + i0 + tx] = tile[tx][r];
    }
}

// ============================================================================
// Kernel 4: out += d_i * (A @ sprime) [+ d_i^2*sup_i + bias on k-split 0]
// mma.sync tf32 GEMM, CTA tile M128 x N128, K split in 2, KTILE=64 with a
// 3-stage TMA pipeline. 8 compute warps (2x4 MxN, 64x32 per warp) + producer.
// (Best-known config from R13 — unchanged this round.)
// ============================================================================
#define STAGES 3
#define MTILE 128
#define KTILE 64
#define KSPLITS 2
#define KSPAN (NN / KSPLITS)        // 4096
#define GEMM_ITERS (KSPAN / KTILE)  // 64

#define OFF_FULL(s)  ((s) * 8)
#define OFF_EMPTY(s) (64 + (s) * 8)
#define BOX_BYTES 16384             // one TMA box: 128 rows * 32 floats
#define A_TILE_BYTES 32768          // two boxes (k 0-31, k 32-63)
#define STAGE_BYTES  65536          // A + B
#define OFF_A(s)   (1024 + (s) * STAGE_BYTES)
#define OFF_B(s)   (OFF_A(s) + A_TILE_BYTES)
#define GEMM_SMEM  (1024 + STAGES * STAGE_BYTES)   // 197632 -> 1 CTA/SM

__global__ void __launch_bounds__(288, 1) gcn_gemm_kernel(
    const __grid_constant__ CUtensorMap tma_a,
    const __grid_constant__ CUtensorMap tma_b,
    const float* __restrict__ dinv,
    const float* __restrict__ sup,
    const float* __restrict__ bias,
    float* __restrict__ out)
{
    extern __shared__ char smem[];
    uint32_t sb = smem_u32(smem);
    const int tid = threadIdx.x, wid = tid >> 5, lane = tid & 31;
    const int m_base = blockIdx.x * MTILE;
    const int k_base = blockIdx.y * KSPAN;

    if (tid == 0) {
        #pragma unroll
        for (int s = 0; s < STAGES; s++) {
            MBARRIER_INIT(sb + OFF_FULL(s), 1);   // producer arrive + tx
            MBARRIER_INIT(sb + OFF_EMPTY(s), 8);  // one elect-arrive per consumer warp
        }
        asm volatile("fence.mbarrier_init.release.cluster;" ::: "memory");
    }
    __syncthreads();

    if (wid == 8) {
        // ---- TMA producer warp: 4 boxes per stage (A k-lo/hi, B k-lo/hi) ----
        int st = 0, ph = 1;   // flipped phase: first empty-wait passes immediately
        for (int it = 0; it < GEMM_ITERS; it++) {
            MBARRIER_WAIT_PARITY_RELAXED(sb + OFF_EMPTY(st), ph);
            if (elect_one_pred()) {
                MBARRIER_EXPECT_TX(sb + OFF_FULL(st), STAGE_BYTES);
                int kx = k_base + it * KTILE;
                TMA_LOAD_2D(sb + OFF_A(st),             &tma_a, kx,      m_base, sb + OFF_FULL(st));
                TMA_LOAD_2D(sb + OFF_A(st) + BOX_BYTES, &tma_a, kx + 32, m_base, sb + OFF_FULL(st));
                TMA_LOAD_2D(sb + OFF_B(st),             &tma_b, kx,      0,      sb + OFF_FULL(st));
                TMA_LOAD_2D(sb + OFF_B(st) + BOX_BYTES, &tma_b, kx + 32, 0,      sb + OFF_FULL(st));
            }
            if (++st == STAGES) { st = 0; ph ^= 1; }
        }
        return;  // producer done; no epilogue work
    }

    // ---- consumer warps (0..7): 2x4 (M x N) warp grid, 64x32 per warp ----
    const int g = lane >> 2;            // 0..7
    const int c = lane & 3;             // 0..3
    const int m_off = (wid & 1) * 64;
    const int n_off = (wid >> 1) * 32;
    const uint32_t swz = (uint32_t)g << 4;      // SW128 xor term (rows are 8-aligned)

    // Within-box per-k-step word offsets (include swizzle XOR); box k = ks&3
    uint32_t off0[4], off4[4];
    #pragma unroll
    for (int ks = 0; ks < 4; ks++) {
        off0[ks] = ((uint32_t)((ks * 8 + c) * 4)) ^ swz;
        off4[ks] = ((uint32_t)((ks * 8 + c + 4) * 4)) ^ swz;
    }
    // Fragment row base pointers (stage-0 based; stage/box add imm offsets)
    uint32_t qa[4], qb[4];
    #pragma unroll
    for (int i = 0; i < 4; i++) {
        qa[i] = sb + OFF_A(0) + (uint32_t)(m_off + i * 16 + g) * 128u;
        qb[i] = sb + OFF_B(0) + (uint32_t)(n_off + i * 8 + g) * 128u;
    }

    float acc[4][4][4];
    #pragma unroll
    for (int mi = 0; mi < 4; mi++)
        #pragma unroll
        for (int ni = 0; ni < 4; ni++)
            #pragma unroll
            for (int d = 0; d < 4; d++) acc[mi][ni][d] = 0.f;

    int st = 0, ph = 0;
    for (int it = 0; it < GEMM_ITERS; it++) {
        MBARRIER_WAIT_PARITY(sb + OFF_FULL(st), ph);
        const int soff = st * STAGE_BYTES;
        #pragma unroll
        for (int ks = 0; ks < 8; ks++) {
            const int koff = soff + ((ks >= 4) ? BOX_BYTES : 0);
            const int kk = ks & 3;
            uint32_t a[4][4];
            #pragma unroll
            for (int mi = 0; mi < 4; mi++) {
                uint32_t p0 = qa[mi] + off0[kk];
                uint32_t p4 = qa[mi] + off4[kk];
                a[mi][0] = lds_b32(p0, koff);          // row g,   k=c
                a[mi][1] = lds_b32(p0, koff + 1024);   // row g+8, k=c
                a[mi][2] = lds_b32(p4, koff);          // row g,   k=c+4
                a[mi][3] = lds_b32(p4, koff + 1024);   // row g+8, k=c+4
            }
            uint32_t b[4][2];
            #pragma unroll
            for (int ni = 0; ni < 4; ni++) {
                b[ni][0] = lds_b32(qb[ni] + off0[kk], koff);
                b[ni][1] = lds_b32(qb[ni] + off4[kk], koff);
            }
            #pragma unroll
            for (int mi = 0; mi < 4; mi++)
                #pragma unroll
                for (int ni = 0; ni < 4; ni++)
                    mma_tf32(acc[mi][ni], a[mi], b[ni]);
        }
        // All lanes' LDS for this stage issue before lane0's arrive (warp program
        // order), so a single elect-arrive per warp is sufficient (count=8).
        if (lane == 0) MBARRIER_ARRIVE(sb + OFF_EMPTY(st));
        if (++st == STAGES) { st = 0; ph ^= 1; }
    }

    // ---- epilogue: d_i scale, optional self-loop (dv^2 * sup) + bias, float2 atomics ----
    #pragma unroll
    for (int mi = 0; mi < 4; mi++) {
        int r0 = m_base + m_off + mi * 16 + g;
        int r1 = r0 + 8;
        float dv0 = dinv[r0];
        float dv1 = dinv[r1];
        #pragma unroll
        for (int ni = 0; ni < 4; ni++) {
            int col = n_off + ni * 8 + c * 2;
            float2 v0 = make_float2(dv0 * acc[mi][ni][0], dv0 * acc[mi][ni][1]);
            float2 v1 = make_float2(dv1 * acc[mi][ni][2], dv1 * acc[mi][ni][3]);
            if (blockIdx.y == 0) {
                float s00 = sup[r0 * DD + col], s01 = sup[r0 * DD + col + 1];
                float s10 = sup[r1 * DD + col], s11 = sup[r1 * DD + col + 1];
                v0.x += dv0 * dv0 * s00 + bias[col];
                v0.y += dv0 * dv0 * s01 + bias[col + 1];
                v1.x += dv1 * dv1 * s10 + bias[col];
                v1.y += dv1 * dv1 * s11 + bias[col + 1];
            }
            atomicAdd((float2*)&out[r0 * DD + col], v0);
            atomicAdd((float2*)&out[r1 * DD + col], v1);
        }
    }
}

// ============================================================================
// Host launcher
// ============================================================================
typedef CUresult (*PFN_tmapEncode)(CUtensorMap*, CUtensorMapDataType, cuuint32_t, void*,
                                   const cuuint64_t*, const cuuint64_t*, const cuuint32_t*,
                                   const cuuint32_t*, CUtensorMapInterleave, CUtensorMapSwizzle,
                                   CUtensorMapL2promotion, CUtensorMapFloatOOBfill);

extern "C" void kernel_launch(void* const* d_in, const int* in_sizes, int n_in,
                              void* d_out, int out_size) {
    const float* X    = (const float*)d_in[0];   // [8192,128]
    const float* A    = (const float*)d_in[1];   // [8192,8192]
    const float* W    = (const float*)d_in[2];   // [128,128]
    const float* bias = (const float*)d_in[3];   // [128]
    float* out = (float*)d_out;                  // [8192,128]

    float *sup, *sprimeT, *dinv;
    cudaGetSymbolAddress((void**)&sup,     g_sup);
    cudaGetSymbolAddress((void**)&sprimeT, g_sprimeT);
    cudaGetSymbolAddress((void**)&dinv,    g_dinv);

    // Resolve driver tensor-map encoder without a -lcuda link dependency.
    PFN_tmapEncode encode = nullptr;
    {
        void* fn = nullptr;
        cudaDriverEntryPointQueryResult qr;
        cudaGetDriverEntryPointByVersion("cuTensorMapEncodeTiled", &fn, 12000,
                                         cudaEnableDefault, &qr);
        encode = (PFN_tmapEncode)fn;
    }

    // TMA maps: inner dim = 32 fp32 = 128B (SW128 limit), 128 rows per box.
    CUtensorMap mapA, mapB;
    {
        cuuint64_t dims[2]  = {NN, NN};
        cuuint64_t strides[1] = {(cuuint64_t)NN * sizeof(float)};
        cuuint32_t box[2]   = {32, MTILE};
        cuuint32_t es[2]    = {1, 1};
        encode(&mapA, CU_TENSOR_MAP_DATA_TYPE_FLOAT32, 2, (void*)A,
               dims, strides, box, es,
               CU_TENSOR_MAP_INTERLEAVE_NONE, CU_TENSOR_MAP_SWIZZLE_128B,
               CU_TENSOR_MAP_L2_PROMOTION_L2_128B, CU_TENSOR_MAP_FLOAT_OOB_FILL_NONE);
    }
    {
        cuuint64_t dims[2]  = {NN, DD};
        cuuint64_t strides[1] = {(cuuint64_t)NN * sizeof(float)};
        cuuint32_t box[2]   = {32, 128};
        cuuint32_t es[2]    = {1, 1};
        encode(&mapB, CU_TENSOR_MAP_DATA_TYPE_FLOAT32, 2, (void*)sprimeT,
               dims, strides, box, es,
               CU_TENSOR_MAP_INTERLEAVE_NONE, CU_TENSOR_MAP_SWIZZLE_128B,
               CU_TENSOR_MAP_L2_PROMOTION_L2_128B, CU_TENSOR_MAP_FLOAT_OOB_FILL_NONE);
    }

    cudaFuncSetAttribute(gcn_gemm_kernel, cudaFuncAttributeMaxDynamicSharedMemorySize, GEMM_SMEM);

    // Pipeline of kernels on the default (captured) stream.
    support_kernel<<<NN / 8, 256>>>(X, W, sup);
    rowsum_kernel<<<NN, 256>>>((const float4*)A, dinv);
    scale_transpose_kernel<<<dim3(NN / 32, DD / 32), dim3(32, 8)>>>(sup, dinv, sprimeT);
    cudaMemsetAsync(d_out, 0, (size_t)NN * DD * sizeof(float));
    gcn_gemm_kernel<<<dim3(NN / MTILE, KSPLITS), 288, GEMM_SMEM>>>(mapA, mapB, dinv, sup, bias, out);
}

// round 16
// speedup vs baseline: 1.1932x; 1.0849x over previous
#include <cuda_runtime.h>
#include <cuda.h>
#include <cstdint>

// ============================================================================
// Problem constants: N=8192 nodes, D_IN=D_OUT=128
// ============================================================================
#define NN 8192
#define DD 128

// Scratch (allocation-free rule: __device__ globals)
__device__ __align__(1024) float g_sup[NN * DD];       // X @ W
__device__ __align__(1024) float g_sprimeT[DD * NN];   // tf32-rounded d ⊙ (X@W), transposed [c][i]
__device__ __align__(1024) float g_dinv[NN];

// ============================================================================
// PTX helpers — only baseline (non sm_103a-gated) instructions.
// ============================================================================
__device__ __forceinline__ uint32_t smem_u32(const void* p) {
    uint32_t a;
    asm("{ .reg .u64 t; cvta.to.shared.u64 t, %1; cvt.u32.u64 %0, t; }" : "=r"(a) : "l"(p));
    return a;
}
__device__ __forceinline__ uint32_t elect_one_pred() {
    uint32_t p;
    asm volatile("{\n\t.reg .pred p;\n\telect.sync _|p, 0xFFFFFFFF;\n\tselp.b32 %0, 1, 0, p;\n\t}" : "=r"(p));
    return p;
}

#define MBARRIER_INIT(addr, cnt) \
    asm volatile("mbarrier.init.shared.b64 [%0], %1;" :: "r"((uint32_t)(addr)), "r"((uint32_t)(cnt)) : "memory")
#define MBARRIER_EXPECT_TX(addr, bytes) \
    asm volatile("mbarrier.arrive.expect_tx.shared.b64 _, [%0], %1;" :: "r"((uint32_t)(addr)), "r"((uint32_t)(bytes)) : "memory")
#define MBARRIER_ARRIVE(addr) \
    asm volatile("mbarrier.arrive.shared.b64 _, [%0];" :: "r"((uint32_t)(addr)) : "memory")

#define MBARRIER_WAIT_PARITY(mbar_smem_addr, phase_parity) do { \
    uint32_t _mbar = (uint32_t)(mbar_smem_addr); \
    uint32_t _parity = (uint32_t)(phase_parity); \
    uint32_t _done; \
    asm volatile("{\n\t.reg .pred p;\n\t" \
        "mbarrier.try_wait.parity.acquire.cta.shared::cta.b64 p, [%1], %2;\n\t" \
        "selp.b32 %0, 1, 0, p;\n\t}" \
        : "=r"(_done) : "r"(_mbar), "r"(_parity) : "memory"); \
    if (!_done) { \
        asm volatile("{\n\t.reg .pred P1;\n\t" \
            "WAIT_LOOP_%=:\n\t" \
            "mbarrier.try_wait.parity.acquire.cta.shared::cta.b64 P1, [%0], %1, 0x989680;\n\t" \
            "@P1 bra.uni WAIT_DONE_%=;\n\t" \
            "bra.uni WAIT_LOOP_%=;\n\t" \
            "WAIT_DONE_%=:\n\t}" \
            :: "r"(_mbar), "r"(_parity) : "memory"); \
    } \
} while(0)

#define MBARRIER_WAIT_PARITY_RELAXED(mbar_smem_addr, phase_parity) do { \
    uint32_t _mbar = (uint32_t)(mbar_smem_addr); \
    uint32_t _parity = (uint32_t)(phase_parity); \
    uint32_t _done; \
    asm volatile("{\n\t.reg .pred p;\n\t" \
        "mbarrier.try_wait.parity.relaxed.cta.shared::cta.b64 p, [%1], %2, 0x989680;\n\t" \
        "selp.b32 %0, 1, 0, p;\n\t}" \
        : "=r"(_done) : "r"(_mbar), "r"(_parity) : "memory"); \
    if (!_done) { \
        asm volatile("{\n\t.reg .pred P1;\n\t" \
            "WAIT_LOOP_%=:\n\t" \
            "mbarrier.try_wait.parity.relaxed.cta.shared::cta.b64 P1, [%0], %1, 0x989680;\n\t" \
            "@P1 bra.uni WAIT_DONE_%=;\n\t" \
            "bra.uni WAIT_LOOP_%=;\n\t" \
            "WAIT_DONE_%=:\n\t}" \
            :: "r"(_mbar), "r"(_parity) : "memory"); \
    } \
} while(0)

#define TMA_LOAD_2D(smem_addr, tmap_ptr, cx, cy, mbar) \
    asm volatile("cp.async.bulk.tensor.2d.shared::cta.global.tile.mbarrier::complete_tx::bytes " \
        "[%0], [%1, {%2, %3}], [%4];" \
        :: "r"((uint32_t)(smem_addr)), "l"(tmap_ptr), "r"((int32_t)(cx)), "r"((int32_t)(cy)), \
           "r"((uint32_t)(mbar)) : "memory")

// Plain ld.shared.b32 — raw fp32 bits fed to tf32 MMA (truncation; no cvt in hot loop)
__device__ __forceinline__ uint32_t lds_b32(uint32_t addr, int imm) {
    uint32_t v;
    asm volatile("ld.shared.b32 %0, [%1];" : "=r"(v) : "r"(addr + imm));
    return v;
}

// m16n8k8 tf32 HMMA (baseline PTX, works on plain sm_103 target)
__device__ __forceinline__ void mma_tf32(float* d, const uint32_t* a, const uint32_t* b) {
    asm volatile(
        "mma.sync.aligned.m16n8k8.row.col.f32.tf32.tf32.f32 "
        "{%0,%1,%2,%3}, {%4,%5,%6,%7}, {%8,%9}, {%0,%1,%2,%3};"
        : "+f"(d[0]), "+f"(d[1]), "+f"(d[2]), "+f"(d[3])
        : "r"(a[0]), "r"(a[1]), "r"(a[2]), "r"(a[3]), "r"(b[0]), "r"(b[1]));
}

// ============================================================================
// Kernel 1 (fused prologue): block-range dispatch of three independent jobs:
//   blocks [0, 8192):     rowsum  -> dinv   (DRAM-bound, scheduled first)
//   blocks [8192, 9216):  support -> sup    (X @ W, hides in rowsum shadow)
//   blocks [9216, 9344):  zero the output buffer (replaces cudaMemsetAsync)
// ============================================================================
#define PRO_ROWSUM  8192
#define PRO_SUPPORT (PRO_ROWSUM + NN / 8)      // 9216
#define PRO_TOTAL   (PRO_SUPPORT + 128)        // 9344

__global__ void __launch_bounds__(256) prologue_kernel(const float* __restrict__ X,
                                                       const float* __restrict__ W,
                                                       const float4* __restrict__ A4,
                                                       float* __restrict__ sup,
                                                       float* __restrict__ dinv,
                                                       float4* __restrict__ out4) {
    __shared__ float sh[8][DD];   // support x-rows; rowsum reuses sh[0][0..7]
    const int b = blockIdx.x;
    const int t = threadIdx.x;
    const int w = t >> 5, lane = t & 31;

    if (b < PRO_ROWSUM) {
        // ---- rowsum: one block per row, 8 front-batched float4 loads/thread ----
        const float4* rp = A4 + (size_t)b * (NN / 4);
        float4 v0 = rp[t];
        float4 v1 = rp[t + 256];
        float4 v2 = rp[t + 512];
        float4 v3 = rp[t + 768];
        float4 v4 = rp[t + 1024];
        float4 v5 = rp[t + 1280];
        float4 v6 = rp[t + 1536];
        float4 v7 = rp[t + 1792];
        float s = ((v0.x + v0.y) + (v0.z + v0.w)) + ((v1.x + v1.y) + (v1.z + v1.w))
                + ((v2.x + v2.y) + (v2.z + v2.w)) + ((v3.x + v3.y) + (v3.z + v3.w))
                + ((v4.x + v4.y) + (v4.z + v4.w)) + ((v5.x + v5.y) + (v5.z + v5.w))
                + ((v6.x + v6.y) + (v6.z + v6.w)) + ((v7.x + v7.y) + (v7.z + v7.w));
        #pragma unroll
        for (int o = 16; o > 0; o >>= 1) s += __shfl_xor_sync(0xFFFFFFFFu, s, o);
        if (lane == 0) sh[0][w] = s;
        __syncthreads();
        if (t == 0) {
            float tot = (sh[0][0] + sh[0][1]) + (sh[0][2] + sh[0][3])
                      + (sh[0][4] + sh[0][5]) + (sh[0][6] + sh[0][7]);
            dinv[b] = rsqrtf(tot + 1.0f);
        }
    } else if (b < PRO_SUPPORT) {
        // ---- support: one warp per row, 8 rows per block ----
        int row = (b - PRO_ROWSUM) * 8 + w;
        const float4* xr = (const float4*)(X + row * DD);
        ((float4*)sh[w])[lane] = xr[lane];
        __syncwarp();
        float4 acc = make_float4(0.f, 0.f, 0.f, 0.f);
        #pragma unroll 8
        for (int k = 0; k < DD; k++) {
            float xv = sh[w][k];
            float4 wv = *(const float4*)(W + k * DD + lane * 4);
            acc.x = fmaf(xv, wv.x, acc.x);
            acc.y = fmaf(xv, wv.y, acc.y);
            acc.z = fmaf(xv, wv.z, acc.z);
            acc.w = fmaf(xv, wv.w, acc.w);
        }
        *(float4*)(sup + row * DD + lane * 4) = acc;
    } else {
        // ---- zero output: 128 blocks x 256 threads x 8 float4 = 4 MB ----
        int z = b - PRO_SUPPORT;
        const float4 zero4 = make_float4(0.f, 0.f, 0.f, 0.f);
        size_t base = (size_t)z * 2048 + t;
        #pragma unroll
        for (int i = 0; i < 8; i++) out4[base + i * 256] = zero4;
    }
}

// ============================================================================
// Kernel 2: sprimeT = tf32_round(transpose(d ⊙ support))
// ============================================================================
__global__ void __launch_bounds__(256) scale_transpose_kernel(const float* __restrict__ sup,
                                                              const float* __restrict__ dinv,
                                                              float* __restrict__ sprimeT) {
    __shared__ float tile[32][33];
    int i0 = blockIdx.x * 32;
    int c0 = blockIdx.y * 32;
    int tx = threadIdx.x, ty = threadIdx.y;

    #pragma unroll
    for (int r = ty; r < 32; r += 8) {
        int i = i0 + r;
        float v = sup[i * DD + c0 + tx] * dinv[i];
        uint32_t u = __float_as_uint(v);
        asm("cvt.rna.tf32.f32 %0, %0;" : "+r"(u));
        tile[r][tx] = __uint_as_float(u);
    }
    __syncthreads();
    #pragma unroll
    for (int r = ty; r < 32; r += 8) {
        int c = c0 + r;
        sprimeT[(size_t)c * NN + i0 + tx] = tile[tx][r];
    }
}

// ============================================================================
// Kernel 3: persistent GEMM. 148 CTAs, each owns a contiguous chunk of the
// global iteration space gi in [0, 8192): m_tile = gi>>7, k_iter = gi&127.
// Kills wave quantization (makespan 131k -> 114.7k tensor cycles). A chunk
// spans <=2 m-tiles; accumulators flush (atomics) at m-tile boundaries.
// Self-loop + bias added by the CTA that owns k_iter==0 of that m-tile.
// 8 compute warps (2x4 MxN, 64x32 per warp) + 1 TMA producer = 288 threads.
// ============================================================================
#define STAGES 3
#define MTILE 128
#define KTILE 64
#define MTILES (NN / MTILE)             // 64
#define ITERS_PER_M (NN / KTILE)        // 128
#define TOTAL_ITERS (MTILES * ITERS_PER_M)  // 8192
#define GEMM_GRID 148

#define OFF_FULL(s)  ((s) * 8)
#define OFF_EMPTY(s) (64 + (s) * 8)
#define BOX_BYTES 16384             // one TMA box: 128 rows * 32 floats
#define A_TILE_BYTES 32768          // two boxes (k 0-31, k 32-63)
#define STAGE_BYTES  65536          // A + B
#define OFF_A(s)   (1024 + (s) * STAGE_BYTES)
#define OFF_B(s)   (OFF_A(s) + A_TILE_BYTES)
#define GEMM_SMEM  (1024 + STAGES * STAGE_BYTES)   // 197632 -> 1 CTA/SM

__global__ void __launch_bounds__(288, 1) gcn_gemm_kernel(
    const __grid_constant__ CUtensorMap tma_a,
    const __grid_constant__ CUtensorMap tma_b,
    const float* __restrict__ dinv,
    const float* __restrict__ sup,
    const float* __restrict__ bias,
    float* __restrict__ out)
{
    extern __shared__ char smem[];
    uint32_t sb = smem_u32(smem);
    const int tid = threadIdx.x, wid = tid >> 5, lane = tid & 31;

    // Contiguous chunk assignment: first `extra` CTAs get base+1 iters.
    const int base = TOTAL_ITERS / GEMM_GRID;               // 55
    const int extra = TOTAL_ITERS - base * GEMM_GRID;       // 52
    const int cta = blockIdx.x;
    const int start = cta * base + (cta < extra ? cta : extra);
    const int end = start + base + (cta < extra ? 1 : 0);

    if (tid == 0) {
        #pragma unroll
        for (int s = 0; s < STAGES; s++) {
            MBARRIER_INIT(sb + OFF_FULL(s), 1);   // producer arrive + tx
            MBARRIER_INIT(sb + OFF_EMPTY(s), 8);  // one elect-arrive per consumer warp
        }
        asm volatile("fence.mbarrier_init.release.cluster;" ::: "memory");
    }
    __syncthreads();

    if (wid == 8) {
        // ---- TMA producer warp: 4 boxes per stage (A k-lo/hi, B k-lo/hi) ----
        int st = 0, ph = 1;   // flipped phase: first empty-wait passes immediately
        for (int gi = start; gi < end; gi++) {
            const int mt = gi >> 7;
            const int kx = (gi & 127) * KTILE;
            MBARRIER_WAIT_PARITY_RELAXED(sb + OFF_EMPTY(st), ph);
            if (elect_one_pred()) {
                MBARRIER_EXPECT_TX(sb + OFF_FULL(st), STAGE_BYTES);
                TMA_LOAD_2D(sb + OFF_A(st),             &tma_a, kx,      mt * MTILE, sb + OFF_FULL(st));
                TMA_LOAD_2D(sb + OFF_A(st) + BOX_BYTES, &tma_a, kx + 32, mt * MTILE, sb + OFF_FULL(st));
                TMA_LOAD_2D(sb + OFF_B(st),             &tma_b, kx,      0,          sb + OFF_FULL(st));
                TMA_LOAD_2D(sb + OFF_B(st) + BOX_BYTES, &tma_b, kx + 32, 0,          sb + OFF_FULL(st));
            }
            if (++st == STAGES) { st = 0; ph ^= 1; }
        }
        return;  // producer done; no epilogue work
    }

    // ---- consumer warps (0..7): 2x4 (M x N) warp grid, 64x32 per warp ----
    const int g = lane >> 2;            // 0..7
    const int c = lane & 3;             // 0..3
    const int m_off = (wid & 1) * 64;
    const int n_off = (wid >> 1) * 32;
    const uint32_t swz = (uint32_t)g << 4;      // SW128 xor term (rows are 8-aligned)

    // Within-box per-k-step word offsets (include swizzle XOR); box k = ks&3
    uint32_t off0[4], off4[4];
    #pragma unroll
    for (int ks = 0; ks < 4; ks++) {
        off0[ks] = ((uint32_t)((ks * 8 + c) * 4)) ^ swz;
        off4[ks] = ((uint32_t)((ks * 8 + c + 4) * 4)) ^ swz;
    }
    // Fragment row base pointers (stage-0 based; stage/box add imm offsets)
    uint32_t qa[4], qb[4];
    #pragma unroll
    for (int i = 0; i < 4; i++) {
        qa[i] = sb + OFF_A(0) + (uint32_t)(m_off + i * 16 + g) * 128u;
        qb[i] = sb + OFF_B(0) + (uint32_t)(n_off + i * 8 + g) * 128u;
    }

    float acc[4][4][4];
    #pragma unroll
    for (int mi = 0; mi < 4; mi++)
        #pragma unroll
        for (int ni = 0; ni < 4; ni++)
            #pragma unroll
            for (int d = 0; d < 4; d++) acc[mi][ni][d] = 0.f;

    // Flush accumulators for m-tile `mt` (adds self-loop + bias if this CTA
    // owns that tile's k_iter==0, i.e. chunk start <= mt*128), then zero them.
    auto flush = [&](int mt) {
        const int mb = mt * MTILE;
        const bool self = (mt << 7) >= start;
        #pragma unroll
        for (int mi = 0; mi < 4; mi++) {
            int r0 = mb + m_off + mi * 16 + g;
            int r1 = r0 + 8;
            float dv0 = dinv[r0];
            float dv1 = dinv[r1];
            #pragma unroll
            for (int ni = 0; ni < 4; ni++) {
                int col = n_off + ni * 8 + c * 2;
                float2 v0 = make_float2(dv0 * acc[mi][ni][0], dv0 * acc[mi][ni][1]);
                float2 v1 = make_float2(dv1 * acc[mi][ni][2], dv1 * acc[mi][ni][3]);
                if (self) {
                    v0.x += dv0 * dv0 * sup[r0 * DD + col]     + bias[col];
                    v0.y += dv0 * dv0 * sup[r0 * DD + col + 1] + bias[col + 1];
                    v1.x += dv1 * dv1 * sup[r1 * DD + col]     + bias[col];
                    v1.y += dv1 * dv1 * sup[r1 * DD + col + 1] + bias[col + 1];
                }
                atomicAdd((float2*)&out[r0 * DD + col], v0);
                atomicAdd((float2*)&out[r1 * DD + col], v1);
                acc[mi][ni][0] = acc[mi][ni][1] = acc[mi][ni][2] = acc[mi][ni][3] = 0.f;
            }
        }
    };

    int st = 0, ph = 0;
    int cur_m = start >> 7;
    for (int gi = start; gi < end; gi++) {
        const int mt = gi >> 7;
        if (mt != cur_m) { flush(cur_m); cur_m = mt; }
        MBARRIER_WAIT_PARITY(sb + OFF_FULL(st), ph);
        const int soff = st * STAGE_BYTES;
        #pragma unroll
        for (int ks = 0; ks < 8; ks++) {
            const int koff = soff + ((ks >= 4) ? BOX_BYTES : 0);
            const int kk = ks & 3;
            uint32_t a[4][4];
            #pragma unroll
            for (int mi = 0; mi < 4; mi++) {
                uint32_t p0 = qa[mi] + off0[kk];
                uint32_t p4 = qa[mi] + off4[kk];
                a[mi][0] = lds_b32(p0, koff);          // row g,   k=c
                a[mi][1] = lds_b32(p0, koff + 1024);   // row g+8, k=c
                a[mi][2] = lds_b32(p4, koff);          // row g,   k=c+4
                a[mi][3] = lds_b32(p4, koff + 1024);   // row g+8, k=c+4
            }
            uint32_t b[4][2];
            #pragma unroll
            for (int ni = 0; ni < 4; ni++) {
                b[ni][0] = lds_b32(qb[ni] + off0[kk], koff);
                b[ni][1] = lds_b32(qb[ni] + off4[kk], koff);
            }
            #pragma unroll
            for (int mi = 0; mi < 4; mi++)
                #pragma unroll
                for (int ni = 0; ni < 4; ni++)
                    mma_tf32(acc[mi][ni], a[mi], b[ni]);
        }
        // All lanes' LDS for this stage issue before lane0's arrive (warp program
        // order), so a single elect-arrive per warp is sufficient (count=8).
        if (lane == 0) MBARRIER_ARRIVE(sb + OFF_EMPTY(st));
        if (++st == STAGES) { st = 0; ph ^= 1; }
    }
    flush(cur_m);
}

// ============================================================================
// Host launcher
// ============================================================================
typedef CUresult (*PFN_tmapEncode)(CUtensorMap*, CUtensorMapDataType, cuuint32_t, void*,
                                   const cuuint64_t*, const cuuint64_t*, const cuuint32_t*,
                                   const cuuint32_t*, CUtensorMapInterleave, CUtensorMapSwizzle,
                                   CUtensorMapL2promotion, CUtensorMapFloatOOBfill);

extern "C" void kernel_launch(void* const* d_in, const int* in_sizes, int n_in,
                              void* d_out, int out_size) {
    const float* X    = (const float*)d_in[0];   // [8192,128]
    const float* A    = (const float*)d_in[1];   // [8192,8192]
    const float* W    = (const float*)d_in[2];   // [128,128]
    const float* bias = (const float*)d_in[3];   // [128]
    float* out = (float*)d_out;                  // [8192,128]

    float *sup, *sprimeT, *dinv;
    cudaGetSymbolAddress((void**)&sup,     g_sup);
    cudaGetSymbolAddress((void**)&sprimeT, g_sprimeT);
    cudaGetSymbolAddress((void**)&dinv,    g_dinv);

    // Resolve driver tensor-map encoder without a -lcuda link dependency.
    PFN_tmapEncode encode = nullptr;
    {
        void* fn = nullptr;
        cudaDriverEntryPointQueryResult qr;
        cudaGetDriverEntryPointByVersion("cuTensorMapEncodeTiled", &fn, 12000,
                                         cudaEnableDefault, &qr);
        encode = (PFN_tmapEncode)fn;
    }

    // TMA maps: inner dim = 32 fp32 = 128B (SW128 limit), 128 rows per box.
    CUtensorMap mapA, mapB;
    {
        cuuint64_t dims[2]  = {NN, NN};
        cuuint64_t strides[1] = {(cuuint64_t)NN * sizeof(float)};
        cuuint32_t box[2]   = {32, MTILE};
        cuuint32_t es[2]    = {1, 1};
        encode(&mapA, CU_TENSOR_MAP_DATA_TYPE_FLOAT32, 2, (void*)A,
               dims, strides, box, es,
               CU_TENSOR_MAP_INTERLEAVE_NONE, CU_TENSOR_MAP_SWIZZLE_128B,
               CU_TENSOR_MAP_L2_PROMOTION_L2_128B, CU_TENSOR_MAP_FLOAT_OOB_FILL_NONE);
    }
    {
        cuuint64_t dims[2]  = {NN, DD};
        cuuint64_t strides[1] = {(cuuint64_t)NN * sizeof(float)};
        cuuint32_t box[2]   = {32, 128};
        cuuint32_t es[2]    = {1, 1};
        encode(&mapB, CU_TENSOR_MAP_DATA_TYPE_FLOAT32, 2, (void*)sprimeT,
               dims, strides, box, es,
               CU_TENSOR_MAP_INTERLEAVE_NONE, CU_TENSOR_MAP_SWIZZLE_128B,
               CU_TENSOR_MAP_L2_PROMOTION_L2_128B, CU_TENSOR_MAP_FLOAT_OOB_FILL_NONE);
    }

    cudaFuncSetAttribute(gcn_gemm_kernel, cudaFuncAttributeMaxDynamicSharedMemorySize, GEMM_SMEM);

    // 3 launches: fused prologue (rowsum + support + out-zero), transpose, GEMM.
    prologue_kernel<<<PRO_TOTAL, 256>>>(X, W, (const float4*)A, sup, dinv, (float4*)out);
    scale_transpose_kernel<<<dim3(NN / 32, DD / 32), dim3(32, 8)>>>(sup, dinv, sprimeT);
    gcn_gemm_kernel<<<GEMM_GRID, 288, GEMM_SMEM>>>(mapA, mapB, dinv, sup, bias, out);
}

// round 17
// speedup vs baseline: 1.2112x; 1.0151x over previous
#include <cuda_runtime.h>
#include <cuda.h>
#include <cstdint>

// ============================================================================
// Problem constants: N=8192 nodes, D_IN=D_OUT=128
// ============================================================================
#define NN 8192
#define DD 128

// Scratch (allocation-free rule: __device__ globals)
__device__ __align__(1024) float g_sup[NN * DD];       // X @ W
__device__ __align__(1024) float g_sprimeT[DD * NN];   // tf32-rounded d ⊙ (X@W), transposed [c][i]
__device__ __align__(1024) float g_dinv[NN];

// ============================================================================
// PTX helpers — only baseline (non sm_103a-gated) instructions.
// ============================================================================
__device__ __forceinline__ uint32_t smem_u32(const void* p) {
    uint32_t a;
    asm("{ .reg .u64 t; cvta.to.shared.u64 t, %1; cvt.u32.u64 %0, t; }" : "=r"(a) : "l"(p));
    return a;
}
__device__ __forceinline__ uint32_t elect_one_pred() {
    uint32_t p;
    asm volatile("{\n\t.reg .pred p;\n\telect.sync _|p, 0xFFFFFFFF;\n\tselp.b32 %0, 1, 0, p;\n\t}" : "=r"(p));
    return p;
}

#define MBARRIER_INIT(addr, cnt) \
    asm volatile("mbarrier.init.shared.b64 [%0], %1;" :: "r"((uint32_t)(addr)), "r"((uint32_t)(cnt)) : "memory")
#define MBARRIER_EXPECT_TX(addr, bytes) \
    asm volatile("mbarrier.arrive.expect_tx.shared.b64 _, [%0], %1;" :: "r"((uint32_t)(addr)), "r"((uint32_t)(bytes)) : "memory")
#define MBARRIER_ARRIVE(addr) \
    asm volatile("mbarrier.arrive.shared.b64 _, [%0];" :: "r"((uint32_t)(addr)) : "memory")

#define MBARRIER_WAIT_PARITY(mbar_smem_addr, phase_parity) do { \
    uint32_t _mbar = (uint32_t)(mbar_smem_addr); \
    uint32_t _parity = (uint32_t)(phase_parity); \
    uint32_t _done; \
    asm volatile("{\n\t.reg .pred p;\n\t" \
        "mbarrier.try_wait.parity.acquire.cta.shared::cta.b64 p, [%1], %2;\n\t" \
        "selp.b32 %0, 1, 0, p;\n\t}" \
        : "=r"(_done) : "r"(_mbar), "r"(_parity) : "memory"); \
    if (!_done) { \
        asm volatile("{\n\t.reg .pred P1;\n\t" \
            "WAIT_LOOP_%=:\n\t" \
            "mbarrier.try_wait.parity.acquire.cta.shared::cta.b64 P1, [%0], %1, 0x989680;\n\t" \
            "@P1 bra.uni WAIT_DONE_%=;\n\t" \
            "bra.uni WAIT_LOOP_%=;\n\t" \
            "WAIT_DONE_%=:\n\t}" \
            :: "r"(_mbar), "r"(_parity) : "memory"); \
    } \
} while(0)

#define MBARRIER_WAIT_PARITY_RELAXED(mbar_smem_addr, phase_parity) do { \
    uint32_t _mbar = (uint32_t)(mbar_smem_addr); \
    uint32_t _parity = (uint32_t)(phase_parity); \
    uint32_t _done; \
    asm volatile("{\n\t.reg .pred p;\n\t" \
        "mbarrier.try_wait.parity.relaxed.cta.shared::cta.b64 p, [%1], %2, 0x989680;\n\t" \
        "selp.b32 %0, 1, 0, p;\n\t}" \
        : "=r"(_done) : "r"(_mbar), "r"(_parity) : "memory"); \
    if (!_done) { \
        asm volatile("{\n\t.reg .pred P1;\n\t" \
            "WAIT_LOOP_%=:\n\t" \
            "mbarrier.try_wait.parity.relaxed.cta.shared::cta.b64 P1, [%0], %1, 0x989680;\n\t" \
            "@P1 bra.uni WAIT_DONE_%=;\n\t" \
            "bra.uni WAIT_LOOP_%=;\n\t" \
            "WAIT_DONE_%=:\n\t}" \
            :: "r"(_mbar), "r"(_parity) : "memory"); \
    } \
} while(0)

#define TMA_LOAD_2D(smem_addr, tmap_ptr, cx, cy, mbar) \
    asm volatile("cp.async.bulk.tensor.2d.shared::cta.global.tile.mbarrier::complete_tx::bytes " \
        "[%0], [%1, {%2, %3}], [%4];" \
        :: "r"((uint32_t)(smem_addr)), "l"(tmap_ptr), "r"((int32_t)(cx)), "r"((int32_t)(cy)), \
           "r"((uint32_t)(mbar)) : "memory")

// Plain ld.shared.b32 — raw fp32 bits fed to tf32 MMA (truncation; no cvt in hot loop)
__device__ __forceinline__ uint32_t lds_b32(uint32_t addr, int imm) {
    uint32_t v;
    asm volatile("ld.shared.b32 %0, [%1];" : "=r"(v) : "r"(addr + imm));
    return v;
}

// m16n8k8 tf32 HMMA (baseline PTX, works on plain sm_103 target)
__device__ __forceinline__ void mma_tf32(float* d, const uint32_t* a, const uint32_t* b) {
    asm volatile(
        "mma.sync.aligned.m16n8k8.row.col.f32.tf32.tf32.f32 "
        "{%0,%1,%2,%3}, {%4,%5,%6,%7}, {%8,%9}, {%0,%1,%2,%3};"
        : "+f"(d[0]), "+f"(d[1]), "+f"(d[2]), "+f"(d[3])
        : "r"(a[0]), "r"(a[1]), "r"(a[2]), "r"(a[3]), "r"(b[0]), "r"(b[1]));
}

// ============================================================================
// Kernel 1 (fused prologue): block-range dispatch, persistent pipelined rowsum.
//   blocks [0, 1036):        persistent rowsum (7/SM, rows b, b+1036, ... ; each
//                            iteration prefetches the NEXT row's 8 float4 loads
//                            before the reduce, so DRAM demand never pauses)
//   blocks [1036, 1164):     zero output (fills the 8th block slot in wave 1)
//   blocks [1164, 2188):     support = X @ W (short; cycles through 8th slot)
// ============================================================================
#define RS_BLOCKS  1036                       // 7 * 148
#define PRO_ZERO   RS_BLOCKS                  // 1036
#define PRO_SUP    (PRO_ZERO + 128)           // 1164
#define PRO_TOTAL  (PRO_SUP + NN / 8)         // 2188

__global__ void __launch_bounds__(256) prologue_kernel(const float* __restrict__ X,
                                                       const float* __restrict__ W,
                                                       const float4* __restrict__ A4,
                                                       float* __restrict__ sup,
                                                       float* __restrict__ dinv,
                                                       float4* __restrict__ out4) {
    __shared__ float sh[8][DD];   // support x-rows; rowsum reuses sh[0][0..7]
    const int b = blockIdx.x;
    const int t = threadIdx.x;
    const int w = t >> 5, lane = t & 31;

    if (b < RS_BLOCKS) {
        // ---- persistent pipelined rowsum ----
        int row = b;
        const float4* rp = A4 + (size_t)row * (NN / 4);
        float4 v0 = rp[t],        v1 = rp[t + 256],  v2 = rp[t + 512],  v3 = rp[t + 768];
        float4 v4 = rp[t + 1024], v5 = rp[t + 1280], v6 = rp[t + 1536], v7 = rp[t + 1792];
        while (true) {
            // consume current row
            float s = ((v0.x + v0.y) + (v0.z + v0.w)) + ((v1.x + v1.y) + (v1.z + v1.w))
                    + ((v2.x + v2.y) + (v2.z + v2.w)) + ((v3.x + v3.y) + (v3.z + v3.w))
                    + ((v4.x + v4.y) + (v4.z + v4.w)) + ((v5.x + v5.y) + (v5.z + v5.w))
                    + ((v6.x + v6.y) + (v6.z + v6.w)) + ((v7.x + v7.y) + (v7.z + v7.w));
            // prefetch next row BEFORE the reduce — loads fly during shuffles/syncs
            const int next = row + RS_BLOCKS;
            if (next < NN) {
                const float4* np = A4 + (size_t)next * (NN / 4);
                v0 = np[t];        v1 = np[t + 256];  v2 = np[t + 512];  v3 = np[t + 768];
                v4 = np[t + 1024]; v5 = np[t + 1280]; v6 = np[t + 1536]; v7 = np[t + 1792];
            }
            #pragma unroll
            for (int o = 16; o > 0; o >>= 1) s += __shfl_xor_sync(0xFFFFFFFFu, s, o);
            if (lane == 0) sh[0][w] = s;
            __syncthreads();
            if (t == 0) {
                float tot = (sh[0][0] + sh[0][1]) + (sh[0][2] + sh[0][3])
                          + (sh[0][4] + sh[0][5]) + (sh[0][6] + sh[0][7]);
                dinv[row] = rsqrtf(tot + 1.0f);
            }
            if (next >= NN) break;
            row = next;
            __syncthreads();   // sh safe for next iteration
        }
    } else if (b < PRO_SUP) {
        // ---- zero output: 128 blocks x 256 threads x 8 float4 = 4 MB ----
        int z = b - PRO_ZERO;
        const float4 zero4 = make_float4(0.f, 0.f, 0.f, 0.f);
        size_t base = (size_t)z * 2048 + t;
        #pragma unroll
        for (int i = 0; i < 8; i++) out4[base + i * 256] = zero4;
    } else {
        // ---- support: one warp per row, 8 rows per block ----
        int row = (b - PRO_SUP) * 8 + w;
        const float4* xr = (const float4*)(X + row * DD);
        ((float4*)sh[w])[lane] = xr[lane];
        __syncwarp();
        float4 acc = make_float4(0.f, 0.f, 0.f, 0.f);
        #pragma unroll 8
        for (int k = 0; k < DD; k++) {
            float xv = sh[w][k];
            float4 wv = *(const float4*)(W + k * DD + lane * 4);
            acc.x = fmaf(xv, wv.x, acc.x);
            acc.y = fmaf(xv, wv.y, acc.y);
            acc.z = fmaf(xv, wv.z, acc.z);
            acc.w = fmaf(xv, wv.w, acc.w);
        }
        *(float4*)(sup + row * DD + lane * 4) = acc;
    }
}

// ============================================================================
// Kernel 2: sprimeT = tf32_round(transpose(d ⊙ support))
// ============================================================================
__global__ void __launch_bounds__(256) scale_transpose_kernel(const float* __restrict__ sup,
                                                              const float* __restrict__ dinv,
                                                              float* __restrict__ sprimeT) {
    __shared__ float tile[32][33];
    int i0 = blockIdx.x * 32;
    int c0 = blockIdx.y * 32;
    int tx = threadIdx.x, ty = threadIdx.y;

    #pragma unroll
    for (int r = ty; r < 32; r += 8) {
        int i = i0 + r;
        float v = sup[i * DD + c0 + tx] * dinv[i];
        uint32_t u = __float_as_uint(v);
        asm("cvt.rna.tf32.f32 %0, %0;" : "+r"(u));
        tile[r][tx] = __uint_as_float(u);
    }
    __syncthreads();
    #pragma unroll
    for (int r = ty; r < 32; r += 8) {
        int c = c0 + r;
        sprimeT[(size_t)c * NN + i0 + tx] = tile[tx][r];
    }
}

// ============================================================================
// Kernel 3: persistent GEMM (unchanged from R16 — best-known config).
// 148 CTAs, contiguous chunks of gi in [0, 8192): m_tile=gi>>7, k_iter=gi&127.
// 8 compute warps (2x4 MxN, 64x32 per warp) + 1 TMA producer = 288 threads.
// ============================================================================
#define STAGES 3
#define MTILE 128
#define KTILE 64
#define MTILES (NN / MTILE)             // 64
#define ITERS_PER_M (NN / KTILE)        // 128
#define TOTAL_ITERS (MTILES * ITERS_PER_M)  // 8192
#define GEMM_GRID 148

#define OFF_FULL(s)  ((s) * 8)
#define OFF_EMPTY(s) (64 + (s) * 8)
#define BOX_BYTES 16384             // one TMA box: 128 rows * 32 floats
#define A_TILE_BYTES 32768          // two boxes (k 0-31, k 32-63)
#define STAGE_BYTES  65536          // A + B
#define OFF_A(s)   (1024 + (s) * STAGE_BYTES)
#define OFF_B(s)   (OFF_A(s) + A_TILE_BYTES)
#define GEMM_SMEM  (1024 + STAGES * STAGE_BYTES)   // 197632 -> 1 CTA/SM

__global__ void __launch_bounds__(288, 1) gcn_gemm_kernel(
    const __grid_constant__ CUtensorMap tma_a,
    const __grid_constant__ CUtensorMap tma_b,
    const float* __restrict__ dinv,
    const float* __restrict__ sup,
    const float* __restrict__ bias,
    float* __restrict__ out)
{
    extern __shared__ char smem[];
    uint32_t sb = smem_u32(smem);
    const int tid = threadIdx.x, wid = tid >> 5, lane = tid & 31;

    // Contiguous chunk assignment: first `extra` CTAs get base+1 iters.
    const int base = TOTAL_ITERS / GEMM_GRID;               // 55
    const int extra = TOTAL_ITERS - base * GEMM_GRID;       // 52
    const int cta = blockIdx.x;
    const int start = cta * base + (cta < extra ? cta : extra);
    const int end = start + base + (cta < extra ? 1 : 0);

    if (tid == 0) {
        #pragma unroll
        for (int s = 0; s < STAGES; s++) {
            MBARRIER_INIT(sb + OFF_FULL(s), 1);   // producer arrive + tx
            MBARRIER_INIT(sb + OFF_EMPTY(s), 8);  // one elect-arrive per consumer warp
        }
        asm volatile("fence.mbarrier_init.release.cluster;" ::: "memory");
    }
    __syncthreads();

    if (wid == 8) {
        // ---- TMA producer warp: 4 boxes per stage (A k-lo/hi, B k-lo/hi) ----
        int st = 0, ph = 1;   // flipped phase: first empty-wait passes immediately
        for (int gi = start; gi < end; gi++) {
            const int mt = gi >> 7;
            const int kx = (gi & 127) * KTILE;
            MBARRIER_WAIT_PARITY_RELAXED(sb + OFF_EMPTY(st), ph);
            if (elect_one_pred()) {
                MBARRIER_EXPECT_TX(sb + OFF_FULL(st), STAGE_BYTES);
                TMA_LOAD_2D(sb + OFF_A(st),             &tma_a, kx,      mt * MTILE, sb + OFF_FULL(st));
                TMA_LOAD_2D(sb + OFF_A(st) + BOX_BYTES, &tma_a, kx + 32, mt * MTILE, sb + OFF_FULL(st));
                TMA_LOAD_2D(sb + OFF_B(st),             &tma_b, kx,      0,          sb + OFF_FULL(st));
                TMA_LOAD_2D(sb + OFF_B(st) + BOX_BYTES, &tma_b, kx + 32, 0,          sb + OFF_FULL(st));
            }
            if (++st == STAGES) { st = 0; ph ^= 1; }
        }
        return;  // producer done; no epilogue work
    }

    // ---- consumer warps (0..7): 2x4 (M x N) warp grid, 64x32 per warp ----
    const int g = lane >> 2;            // 0..7
    const int c = lane & 3;             // 0..3
    const int m_off = (wid & 1) * 64;
    const int n_off = (wid >> 1) * 32;
    const uint32_t swz = (uint32_t)g << 4;      // SW128 xor term (rows are 8-aligned)

    // Within-box per-k-step word offsets (include swizzle XOR); box k = ks&3
    uint32_t off0[4], off4[4];
    #pragma unroll
    for (int ks = 0; ks < 4; ks++) {
        off0[ks] = ((uint32_t)((ks * 8 + c) * 4)) ^ swz;
        off4[ks] = ((uint32_t)((ks * 8 + c + 4) * 4)) ^ swz;
    }
    // Fragment row base pointers (stage-0 based; stage/box add imm offsets)
    uint32_t qa[4], qb[4];
    #pragma unroll
    for (int i = 0; i < 4; i++) {
        qa[i] = sb + OFF_A(0) + (uint32_t)(m_off + i * 16 + g) * 128u;
        qb[i] = sb + OFF_B(0) + (uint32_t)(n_off + i * 8 + g) * 128u;
    }

    float acc[4][4][4];
    #pragma unroll
    for (int mi = 0; mi < 4; mi++)
        #pragma unroll
        for (int ni = 0; ni < 4; ni++)
            #pragma unroll
            for (int d = 0; d < 4; d++) acc[mi][ni][d] = 0.f;

    // Flush accumulators for m-tile `mt` (adds self-loop + bias if this CTA
    // owns that tile's k_iter==0, i.e. chunk start <= mt*128), then zero them.
    auto flush = [&](int mt) {
        const int mb = mt * MTILE;
        const bool self = (mt << 7) >= start;
        #pragma unroll
        for (int mi = 0; mi < 4; mi++) {
            int r0 = mb + m_off + mi * 16 + g;
            int r1 = r0 + 8;
            float dv0 = dinv[r0];
            float dv1 = dinv[r1];
            #pragma unroll
            for (int ni = 0; ni < 4; ni++) {
                int col = n_off + ni * 8 + c * 2;
                float2 v0 = make_float2(dv0 * acc[mi][ni][0], dv0 * acc[mi][ni][1]);
                float2 v1 = make_float2(dv1 * acc[mi][ni][2], dv1 * acc[mi][ni][3]);
                if (self) {
                    v0.x += dv0 * dv0 * sup[r0 * DD + col]     + bias[col];
                    v0.y += dv0 * dv0 * sup[r0 * DD + col + 1] + bias[col + 1];
                    v1.x += dv1 * dv1 * sup[r1 * DD + col]     + bias[col];
                    v1.y += dv1 * dv1 * sup[r1 * DD + col + 1] + bias[col + 1];
                }
                atomicAdd((float2*)&out[r0 * DD + col], v0);
                atomicAdd((float2*)&out[r1 * DD + col], v1);
                acc[mi][ni][0] = acc[mi][ni][1] = acc[mi][ni][2] = acc[mi][ni][3] = 0.f;
            }
        }
    };

    int st = 0, ph = 0;
    int cur_m = start >> 7;
    for (int gi = start; gi < end; gi++) {
        const int mt = gi >> 7;
        if (mt != cur_m) { flush(cur_m); cur_m = mt; }
        MBARRIER_WAIT_PARITY(sb + OFF_FULL(st), ph);
        const int soff = st * STAGE_BYTES;
        #pragma unroll
        for (int ks = 0; ks < 8; ks++) {
            const int koff = soff + ((ks >= 4) ? BOX_BYTES : 0);
            const int kk = ks & 3;
            uint32_t a[4][4];
            #pragma unroll
            for (int mi = 0; mi < 4; mi++) {
                uint32_t p0 = qa[mi] + off0[kk];
                uint32_t p4 = qa[mi] + off4[kk];
                a[mi][0] = lds_b32(p0, koff);          // row g,   k=c
                a[mi][1] = lds_b32(p0, koff + 1024);   // row g+8, k=c
                a[mi][2] = lds_b32(p4, koff);          // row g,   k=c+4
                a[mi][3] = lds_b32(p4, koff + 1024);   // row g+8, k=c+4
            }
            uint32_t b[4][2];
            #pragma unroll
            for (int ni = 0; ni < 4; ni++) {
                b[ni][0] = lds_b32(qb[ni] + off0[kk], koff);
                b[ni][1] = lds_b32(qb[ni] + off4[kk], koff);
            }
            #pragma unroll
            for (int mi = 0; mi < 4; mi++)
                #pragma unroll
                for (int ni = 0; ni < 4; ni++)
                    mma_tf32(acc[mi][ni], a[mi], b[ni]);
        }
        // All lanes' LDS for this stage issue before lane0's arrive (warp program
        // order), so a single elect-arrive per warp is sufficient (count=8).
        if (lane == 0) MBARRIER_ARRIVE(sb + OFF_EMPTY(st));
        if (++st == STAGES) { st = 0; ph ^= 1; }
    }
    flush(cur_m);
}

// ============================================================================
// Host launcher
// ============================================================================
typedef CUresult (*PFN_tmapEncode)(CUtensorMap*, CUtensorMapDataType, cuuint32_t, void*,
                                   const cuuint64_t*, const cuuint64_t*, const cuuint32_t*,
                                   const cuuint32_t*, CUtensorMapInterleave, CUtensorMapSwizzle,
                                   CUtensorMapL2promotion, CUtensorMapFloatOOBfill);

extern "C" void kernel_launch(void* const* d_in, const int* in_sizes, int n_in,
                              void* d_out, int out_size) {
    const float* X    = (const float*)d_in[0];   // [8192,128]
    const float* A    = (const float*)d_in[1];   // [8192,8192]
    const float* W    = (const float*)d_in[2];   // [128,128]
    const float* bias = (const float*)d_in[3];   // [128]
    float* out = (float*)d_out;                  // [8192,128]

    float *sup, *sprimeT, *dinv;
    cudaGetSymbolAddress((void**)&sup,     g_sup);
    cudaGetSymbolAddress((void**)&sprimeT, g_sprimeT);
    cudaGetSymbolAddress((void**)&dinv,    g_dinv);

    // Resolve driver tensor-map encoder without a -lcuda link dependency.
    PFN_tmapEncode encode = nullptr;
    {
        void* fn = nullptr;
        cudaDriverEntryPointQueryResult qr;
        cudaGetDriverEntryPointByVersion("cuTensorMapEncodeTiled", &fn, 12000,
                                         cudaEnableDefault, &qr);
        encode = (PFN_tmapEncode)fn;
    }

    // TMA maps: inner dim = 32 fp32 = 128B (SW128 limit), 128 rows per box.
    CUtensorMap mapA, mapB;
    {
        cuuint64_t dims[2]  = {NN, NN};
        cuuint64_t strides[1] = {(cuuint64_t)NN * sizeof(float)};
        cuuint32_t box[2]   = {32, MTILE};
        cuuint32_t es[2]    = {1, 1};
        encode(&mapA, CU_TENSOR_MAP_DATA_TYPE_FLOAT32, 2, (void*)A,
               dims, strides, box, es,
               CU_TENSOR_MAP_INTERLEAVE_NONE, CU_TENSOR_MAP_SWIZZLE_128B,
               CU_TENSOR_MAP_L2_PROMOTION_L2_128B, CU_TENSOR_MAP_FLOAT_OOB_FILL_NONE);
    }
    {
        cuuint64_t dims[2]  = {NN, DD};
        cuuint64_t strides[1] = {(cuuint64_t)NN * sizeof(float)};
        cuuint32_t box[2]   = {32, 128};
        cuuint32_t es[2]    = {1, 1};
        encode(&mapB, CU_TENSOR_MAP_DATA_TYPE_FLOAT32, 2, (void*)sprimeT,
               dims, strides, box, es,
               CU_TENSOR_MAP_INTERLEAVE_NONE, CU_TENSOR_MAP_SWIZZLE_128B,
               CU_TENSOR_MAP_L2_PROMOTION_L2_128B, CU_TENSOR_MAP_FLOAT_OOB_FILL_NONE);
    }

    cudaFuncSetAttribute(gcn_gemm_kernel, cudaFuncAttributeMaxDynamicSharedMemorySize, GEMM_SMEM);

    // 3 launches: fused prologue (persistent rowsum + zero + support), transpose, GEMM.
    prologue_kernel<<<PRO_TOTAL, 256>>>(X, W, (const float4*)A, sup, dinv, (float4*)out);
    scale_transpose_kernel<<<dim3(NN / 32, DD / 32), dim3(32, 8)>>>(sup, dinv, sprimeT);
    gcn_gemm_kernel<<<GEMM_GRID, 288, GEMM_SMEM>>>(mapA, mapB, dinv, sup, bias, out);
}